// round 12
// baseline (speedup 1.0000x reference)
#include <cuda_runtime.h>
#include <cuda_bf16.h>
#include <math.h>
#include <stdint.h>

#define BB 4
#define NN 2048
#define DD 1024
#define HH 8
#define NBLK 4
#define MM (BB*NN)          // 8192 rows
#define QKVW 4096
#define QSCALE 0.08838834764831845f   // 1/sqrt(128)
#define INV_N (1.0f/2048.0f)
#define NCK 8
#define CKR (NN/NCK)        // 256

typedef __nv_bfloat16 bf16;

// ---------------- scratch (device globals; no allocation allowed) ----------
__device__ bf16  g_xnh[MM*DD];           // ln output hi
__device__ bf16  g_xnl[MM*DD];           // ln output lo
__device__ bf16  g_qh[BB*HH*NN*128];     // q (scaled) bf16   [b,h,n,d]
__device__ bf16  g_kh[BB*HH*NN*128];     // k bf16
__device__ bf16  g_vh[BB*HH*NN*128];     // v hi
__device__ bf16  g_vl[BB*HH*NN*128];     // v lo
__device__ bf16  g_ath[MM*DD];           // attn output hi
__device__ bf16  g_atl[MM*DD];           // attn output lo
__device__ float g_mv [BB*HH*128];       // fallback: mean over ALL keys of v
__device__ float g_suf[(size_t)BB*HH*NN*128];  // 32 MB suffix sums
__device__ float g_cnt[BB*HH*NN];
__device__ float g_ctv[BB*HH*NCK*128];   // valid-gated chunk totals
__device__ float g_ctu[BB*HH*NCK*128];   // ungated chunk totals
__device__ float g_ckc[BB*HH*NCK];
__device__ bf16  g_wqh[(size_t)NBLK*3072*DD];  // qkv W^T hi  [l][n(3072)][k]
__device__ bf16  g_wql[(size_t)NBLK*3072*DD];
__device__ bf16  g_w2h[(size_t)NBLK*DD*DD];    // out W^T hi
__device__ bf16  g_w2l[(size_t)NBLK*DD*DD];

// ---------------- small helpers ----------------
__device__ __forceinline__ void split2(float x, bf16 &h, bf16 &l) {
    h = __float2bfloat16(x);
    l = __float2bfloat16(x - __bfloat162float(h));
}
__device__ __forceinline__ unsigned short us(bf16 h) { return __bfloat16_as_ushort(h); }
__device__ __forceinline__ uint32_t pkbf(bf16 lo, bf16 hi) {
    return ((uint32_t)us(hi) << 16) | us(lo);
}

// ---------------- HMMA path: mma.sync + ldmatrix + cp.async ---------------
__device__ __forceinline__ uint32_t smem_u32(const void* p) {
    uint32_t a;
    asm("{ .reg .u64 t; cvta.to.shared.u64 t, %1; cvt.u32.u64 %0, t; }"
        : "=r"(a) : "l"(p));
    return a;
}
__device__ __forceinline__ void mma_bf16(float* c, const uint32_t* a, const uint32_t* b) {
    asm volatile(
        "mma.sync.aligned.m16n8k16.row.col.f32.bf16.bf16.f32 "
        "{%0,%1,%2,%3}, {%4,%5,%6,%7}, {%8,%9}, {%0,%1,%2,%3};"
        : "+f"(c[0]), "+f"(c[1]), "+f"(c[2]), "+f"(c[3])
        : "r"(a[0]), "r"(a[1]), "r"(a[2]), "r"(a[3]), "r"(b[0]), "r"(b[1]));
}
__device__ __forceinline__ void ldsm4(uint32_t* r, uint32_t addr) {
    asm volatile("ldmatrix.sync.aligned.m8n8.x4.shared.b16 {%0,%1,%2,%3}, [%4];"
                 : "=r"(r[0]), "=r"(r[1]), "=r"(r[2]), "=r"(r[3]) : "r"(addr));
}
__device__ __forceinline__ void ldsm4t(uint32_t* r, uint32_t addr) {
    asm volatile("ldmatrix.sync.aligned.m8n8.x4.trans.shared.b16 {%0,%1,%2,%3}, [%4];"
                 : "=r"(r[0]), "=r"(r[1]), "=r"(r[2]), "=r"(r[3]) : "r"(addr));
}
__device__ __forceinline__ void cpa16(uint32_t dst, const void* src) {
    asm volatile("cp.async.ca.shared.global [%0], [%1], 16;"
                 :: "r"(dst), "l"(src) : "memory");
}
#define CPA_COMMIT asm volatile("cp.async.commit_group;" ::: "memory")
#define CPA_WAIT1  asm volatile("cp.async.wait_group 1;" ::: "memory")
#define CPA_WAIT0  asm volatile("cp.async.wait_group 0;" ::: "memory")

// ---------------- LayerNorm: one row per block, emits bf16 hi/lo ----------
__global__ void ln_kernel(const float* __restrict__ x,
                          const float* __restrict__ g,
                          const float* __restrict__ bta) {
    __shared__ float sh[8];
    __shared__ float bc[2];
    int row = blockIdx.x;
    int tid = threadIdx.x;
    int lane = tid & 31, wid = tid >> 5;

    const float4* xr = (const float4*)(x + (size_t)row * DD);
    float4 v = xr[tid];

    float s = v.x + v.y + v.z + v.w;
#pragma unroll
    for (int o = 16; o > 0; o >>= 1) s += __shfl_xor_sync(0xffffffffu, s, o);
    if (lane == 0) sh[wid] = s;
    __syncthreads();
    if (tid == 0) {
        float t = 0.f;
#pragma unroll
        for (int i = 0; i < 8; i++) t += sh[i];
        bc[0] = t;
    }
    __syncthreads();
    float mu = bc[0] * (1.f / DD);

    float dx = v.x - mu, dy = v.y - mu, dz = v.z - mu, dw = v.w - mu;

    float sq = dx*dx + dy*dy + dz*dz + dw*dw;
#pragma unroll
    for (int o = 16; o > 0; o >>= 1) sq += __shfl_xor_sync(0xffffffffu, sq, o);
    if (lane == 0) sh[wid] = sq;
    __syncthreads();
    if (tid == 0) {
        float t = 0.f;
#pragma unroll
        for (int i = 0; i < 8; i++) t += sh[i];
        bc[1] = t;
    }
    __syncthreads();
    float rs = rsqrtf(bc[1] * (1.f / DD) + 1e-5f);

    float4 gg = ((const float4*)g)[tid];
    float4 bb = ((const float4*)bta)[tid];
    float o0 = dx * rs * gg.x + bb.x;
    float o1 = dy * rs * gg.y + bb.y;
    float o2 = dz * rs * gg.z + bb.z;
    float o3 = dw * rs * gg.w + bb.w;

    bf16 h0, h1, h2, h3, l0, l1, l2, l3;
    split2(o0, h0, l0); split2(o1, h1, l1);
    split2(o2, h2, l2); split2(o3, h3, l3);
    size_t o = (size_t)row * DD + tid * 4;
    ushort4 hv = {us(h0), us(h1), us(h2), us(h3)};
    ushort4 lv = {us(l0), us(l1), us(l2), us(l3)};
    *(ushort4*)&g_xnh[o] = hv;
    *(ushort4*)&g_xnl[o] = lv;
}

// ---------------- weight transpose + split (once per launch) ---------------
__global__ void wq_cvt(const float* __restrict__ qkvw) {
    __shared__ float t[32][33];
    int l = blockIdx.z;
    int k0 = blockIdx.x * 32, n0 = blockIdx.y * 32;
    int chunk = n0 >> 7, head = chunk / 3, part = chunk % 3;
    int wbase = head * 512 + part * 128 + (n0 & 127);
    const float* W = qkvw + (size_t)l * DD * QKVW;
#pragma unroll
    for (int s = 0; s < 4; s++)
        t[threadIdx.y + 8*s][threadIdx.x] =
            W[(size_t)(k0 + threadIdx.y + 8*s) * QKVW + wbase + threadIdx.x];
    __syncthreads();
#pragma unroll
    for (int s = 0; s < 4; s++) {
        int n = n0 + threadIdx.y + 8*s;
        float v = t[threadIdx.x][threadIdx.y + 8*s];
        bf16 h, lo; split2(v, h, lo);
        size_t o = ((size_t)l * 3072 + n) * DD + k0 + threadIdx.x;
        g_wqh[o] = h; g_wql[o] = lo;
    }
}
__global__ void w2_cvt(const float* __restrict__ outw) {
    __shared__ float t[32][33];
    int l = blockIdx.z;
    int k0 = blockIdx.x * 32, n0 = blockIdx.y * 32;
    const float* W = outw + (size_t)l * DD * DD;
#pragma unroll
    for (int s = 0; s < 4; s++)
        t[threadIdx.y + 8*s][threadIdx.x] =
            W[(size_t)(k0 + threadIdx.y + 8*s) * DD + n0 + threadIdx.x];
    __syncthreads();
#pragma unroll
    for (int s = 0; s < 4; s++) {
        int n = n0 + threadIdx.y + 8*s;
        float v = t[threadIdx.x][threadIdx.y + 8*s];
        bf16 h, lo; split2(v, h, lo);
        size_t o = ((size_t)l * DD + n) * DD + k0 + threadIdx.x;
        g_w2h[o] = h; g_w2l[o] = lo;
    }
}

// ---------------- HMMA GEMM: 128x128 tile, BK=32 --------------------------
// mode 0: C = xn @ Wqkv + bias. q/k column blocks use hi-only (1 MMA);
//         v blocks use split-bf16 (3 MMAs).      grid (24, 64)
// mode 1: X += attn @ Wout + bias (3 MMAs).      grid (8, 64)
#define RSTR 80
#define ST_A_H 0
#define ST_A_L 10240
#define ST_B_H 20480
#define ST_B_L 30720
#define STAGE  40960
#define HM_SMEM (2*STAGE)

__global__ __launch_bounds__(256) void hmma_gemm(int mode, int layer,
                                                 const float* __restrict__ bias,
                                                 float* __restrict__ X) {
    extern __shared__ char smem[];
    uint32_t sb = smem_u32(smem);
    int tid = threadIdx.x;
    int w = tid >> 5, lane = tid & 31;
    int row0 = blockIdx.y * 128;
    int bx = blockIdx.x;
    int part = (mode == 0) ? (bx % 3) : 2;
    bool lo = (mode == 1) || (part == 2);

    const bf16* Ah = ((mode == 0) ? g_xnh : g_ath) + (size_t)row0 * DD;
    const bf16* Al = ((mode == 0) ? g_xnl : g_atl) + (size_t)row0 * DD;
    const bf16* Bh = ((mode == 0) ? (g_wqh + (size_t)layer * 3072 * DD)
                                  : (g_w2h + (size_t)layer * DD * DD))
                     + (size_t)(bx * 128) * DD;
    const bf16* Bl = ((mode == 0) ? (g_wql + (size_t)layer * 3072 * DD)
                                  : (g_w2l + (size_t)layer * DD * DD))
                     + (size_t)(bx * 128) * DD;

    float c[4][4][4];
#pragma unroll
    for (int i = 0; i < 4; i++)
#pragma unroll
        for (int j = 0; j < 4; j++)
#pragma unroll
            for (int q = 0; q < 4; q++) c[i][j][q] = 0.f;

    int wm = w & 1, wn = w >> 1;
    int grp = lane >> 3, r8 = lane & 7;
    int arow = wm * 64 + (grp & 1) * 8 + r8;
    int akb0 = (grp >> 1) * 16;
    int brow = wn * 32 + (grp >> 1) * 8 + r8;
    int bkb0 = (grp & 1) * 16;

    {
        uint32_t s0 = sb;
#pragma unroll
        for (int ch = tid; ch < 512; ch += 256) {
            int row = ch >> 2, cw = ch & 3;
            uint32_t so = row * RSTR + cw * 16;
            size_t go = (size_t)row * DD + cw * 8;
            cpa16(s0 + ST_A_H + so, (const char*)(Ah + go));
            cpa16(s0 + ST_B_H + so, (const char*)(Bh + go));
            if (lo) {
                cpa16(s0 + ST_A_L + so, (const char*)(Al + go));
                cpa16(s0 + ST_B_L + so, (const char*)(Bl + go));
            }
        }
        CPA_COMMIT;
    }

    for (int s = 0; s < 32; s++) {
        if (s + 1 < 32) {
            uint32_t s0 = sb + ((s + 1) & 1) * STAGE;
            int k0 = (s + 1) * 32;
#pragma unroll
            for (int ch = tid; ch < 512; ch += 256) {
                int row = ch >> 2, cw = ch & 3;
                uint32_t so = row * RSTR + cw * 16;
                size_t go = (size_t)row * DD + k0 + cw * 8;
                cpa16(s0 + ST_A_H + so, (const char*)(Ah + go));
                cpa16(s0 + ST_B_H + so, (const char*)(Bh + go));
                if (lo) {
                    cpa16(s0 + ST_A_L + so, (const char*)(Al + go));
                    cpa16(s0 + ST_B_L + so, (const char*)(Bl + go));
                }
            }
        }
        CPA_COMMIT;
        CPA_WAIT1;
        __syncthreads();
        uint32_t base = sb + (s & 1) * STAGE;
#pragma unroll
        for (int k16 = 0; k16 < 2; k16++) {
            uint32_t ah[4][4], al[4][4], bh[2][4], bl[2][4];
            int akb = k16 * 32 + akb0;
            int bkb = k16 * 32 + bkb0;
#pragma unroll
            for (int i = 0; i < 4; i++) {
                uint32_t ao = (uint32_t)(arow + i * 16) * RSTR + akb;
                ldsm4(ah[i], base + ST_A_H + ao);
                if (lo) ldsm4(al[i], base + ST_A_L + ao);
            }
#pragma unroll
            for (int j = 0; j < 2; j++) {
                uint32_t bo = (uint32_t)(brow + j * 16) * RSTR + bkb;
                ldsm4(bh[j], base + ST_B_H + bo);
                if (lo) ldsm4(bl[j], base + ST_B_L + bo);
            }
#pragma unroll
            for (int i = 0; i < 4; i++)
#pragma unroll
                for (int jn = 0; jn < 4; jn++) {
                    const uint32_t* bph = &bh[jn >> 1][(jn & 1) * 2];
                    mma_bf16(c[i][jn], ah[i], bph);
                    if (lo) {
                        const uint32_t* bpl = &bl[jn >> 1][(jn & 1) * 2];
                        mma_bf16(c[i][jn], ah[i], bpl);
                        mma_bf16(c[i][jn], al[i], bph);
                    }
                }
        }
        __syncthreads();
    }
    CPA_WAIT0;

    int quad = lane >> 2, tq = lane & 3;
    if (mode == 0) {
        int head = bx / 3;
        int wcol0 = head * 512 + part * 128;
        bf16* dh = (part == 0) ? g_qh : (part == 1) ? g_kh : g_vh;
        float scale = (part == 0) ? QSCALE : 1.f;
#pragma unroll
        for (int i = 0; i < 4; i++)
#pragma unroll
            for (int half = 0; half < 2; half++) {
                int r = row0 + wm * 64 + i * 16 + quad + half * 8;
                int b = r >> 11, n = r & (NN - 1);
                size_t ro = ((size_t)(b * HH + head) * NN + n) * 128;
#pragma unroll
                for (int jn = 0; jn < 4; jn++) {
                    int col = wn * 32 + jn * 8 + tq * 2;
                    float x0 = (c[i][jn][half*2+0] + bias[wcol0 + col]) * scale;
                    float x1 = (c[i][jn][half*2+1] + bias[wcol0 + col + 1]) * scale;
                    if (part == 2) {
                        bf16 h0, l0, h1, l1;
                        split2(x0, h0, l0); split2(x1, h1, l1);
                        ushort2 hv = {us(h0), us(h1)};
                        ushort2 lv = {us(l0), us(l1)};
                        *(ushort2*)&dh[ro + col] = hv;
                        *(ushort2*)&g_vl[ro + col] = lv;
                    } else {
                        ushort2 hv = {us(__float2bfloat16(x0)),
                                      us(__float2bfloat16(x1))};
                        *(ushort2*)&dh[ro + col] = hv;
                    }
                }
            }
    } else {
        int col0 = bx * 128;
#pragma unroll
        for (int i = 0; i < 4; i++)
#pragma unroll
            for (int half = 0; half < 2; half++) {
                size_t r = row0 + wm * 64 + i * 16 + quad + half * 8;
#pragma unroll
                for (int jn = 0; jn < 4; jn++) {
                    int col = col0 + wn * 32 + jn * 8 + tq * 2;
                    float2 x = *(float2*)&X[r * DD + col];
                    x.x += c[i][jn][half*2+0] + bias[col];
                    x.y += c[i][jn][half*2+1] + bias[col + 1];
                    *(float2*)&X[r * DD + col] = x;
                }
            }
    }
}

// ---------------- suffix sums of V (chunked 2-pass) ------------------------
// SUF[bh][n][d] = sum_{m>n, valid} v[m][d]; CNT[bh][n] = #{m>n valid};
// also meanV over ALL keys (reference's fully-masked fallback).
__global__ void sufA(const int* __restrict__ ids) {   // grid (NCK, 32), 128
    int ck = blockIdx.x, bh = blockIdx.y, b = bh >> 3;
    int d = threadIdx.x;
    size_t vbase = (size_t)bh * NN * 128 + d;
    int m0 = ck * CKR;
    float suf = 0.f, tot = 0.f, cnt = 0.f;
    for (int m = m0 + CKR - 1; m >= m0; m--) {
        float v = __bfloat162float(g_vh[vbase + (size_t)m * 128])
                + __bfloat162float(g_vl[vbase + (size_t)m * 128]);
        g_suf[((size_t)bh * NN + m) * 128 + d] = suf;
        if (d == 0) g_cnt[bh * NN + m] = cnt;
        tot += v;
        if (ids[b * NN + m] != 0) { suf += v; cnt += 1.f; }
    }
    g_ctv[(bh * NCK + ck) * 128 + d] = suf;
    g_ctu[(bh * NCK + ck) * 128 + d] = tot;
    if (d == 0) g_ckc[bh * NCK + ck] = cnt;
}
__global__ void sufB() {                              // grid (NCK, 32), 128
    int ck = blockIdx.x, bh = blockIdx.y;
    int d = threadIdx.x;
    float offs = 0.f, offc = 0.f;
    for (int cc = ck + 1; cc < NCK; cc++) {
        offs += g_ctv[(bh * NCK + cc) * 128 + d];
        offc += g_ckc[bh * NCK + cc];
    }
    if (ck == 0) {
        float t = 0.f;
        for (int cc = 0; cc < NCK; cc++) t += g_ctu[(bh * NCK + cc) * 128 + d];
        g_mv[bh * 128 + d] = t * INV_N;
    }
    int m0 = ck * CKR;
    if (ck < NCK - 1)
        for (int m = m0; m < m0 + CKR; m++) {
            g_suf[((size_t)bh * NN + m) * 128 + d] += offs;
            if (d == 0) g_cnt[bh * NN + m] += offc;
        }
}

// ---------------- attention: HMMA flash, 128-q CTA, 64-key tiles ----------
// p = exp(silu(s)/N) = 1 + d, d = l + l^2/2 (|l| < 3e-3 => Taylor exact).
// Mask part M.V and count come from precomputed SUF/CNT; kernel computes
// only S = Q K^T (bf16 hi-only) and D.V (D split hi/lo, V hi-only).
#define AT_PITCH 272
#define AT_KH 0
#define AT_VH 17408
#define AT_STAGE 34816
#define AT_FLAGS (2*AT_STAGE)
#define ATTN_SMEM (AT_FLAGS + 512 + 512)

__global__ __launch_bounds__(256) void attn_kernel(const int* __restrict__ ids) {
    extern __shared__ char smem[];
    uint32_t sb = smem_u32(smem);
    int* vn  = (int*)(smem + AT_FLAGS);
    int* vmb = (int*)(smem + AT_FLAGS + 512);

    int tid = threadIdx.x;
    int w = tid >> 5, lane = tid & 31;
    int quad = lane >> 2, tq = lane & 3;
    int grp = lane >> 3, r8 = lane & 7;
    int n0 = blockIdx.x * 128;
    int h = blockIdx.y, b = blockIdx.z;
    int bh = b * HH + h;
    size_t base = (size_t)bh * NN * 128;

    // ---- stage Q (hi) into stage area, pull fragments to regs ----
    {
        const char* ph = (const char*)(g_qh + base + (size_t)n0 * 128);
        for (int ch = tid; ch < 2048; ch += 256) {
            int row = ch >> 4, c = ch & 15;
            cpa16(sb + row * AT_PITCH + c * 16, ph + row * 256 + c * 16);
        }
        CPA_COMMIT; CPA_WAIT0;
    }
    if (tid < 128) vn[tid] = (ids[b * NN + n0 + tid] != 0);
    __syncthreads();

    uint32_t qfh[8][4];
    {
        int arow = w * 16 + (grp & 1) * 8 + r8;
#pragma unroll
        for (int kt = 0; kt < 8; kt++) {
            uint32_t ao = (uint32_t)arow * AT_PITCH + kt * 32 + (grp >> 1) * 16;
            ldsm4(qfh[kt], sb + ao);
        }
    }
    __syncthreads();

    float o[16][4];
#pragma unroll
    for (int dt = 0; dt < 16; dt++)
#pragma unroll
        for (int q = 0; q < 4; q++) o[dt][q] = 0.f;
    float run_l[2] = {0.f, 0.f};

    const char* kh = (const char*)(g_kh + base);
    const char* vh = (const char*)(g_vh + base);

    int mt0 = n0 >> 6;
    auto prefetch = [&](int mt, int st) {
        int m0 = mt * 64;
        uint32_t s0 = sb + st * AT_STAGE;
        for (int ch = tid; ch < 1024; ch += 256) {
            int row = ch >> 4, c = ch & 15;
            uint32_t so = row * AT_PITCH + c * 16;
            size_t go = (size_t)(m0 + row) * 256 + c * 16;
            cpa16(s0 + AT_KH + so, kh + go);
            cpa16(s0 + AT_VH + so, vh + go);
        }
        if (tid < 64) vmb[st * 64 + tid] = (ids[b * NN + m0 + tid] != 0);
        CPA_COMMIT;
    };
    prefetch(mt0, 0);

    for (int mt = mt0; mt < NN / 64; mt++) {
        int st = (mt - mt0) & 1;
        if (mt + 1 < NN / 64) { prefetch(mt + 1, st ^ 1); CPA_WAIT1; }
        else                  { CPA_WAIT0; }
        __syncthreads();

        uint32_t stb = sb + st * AT_STAGE;
        int m0 = mt * 64;
        const int* vm = vmb + st * 64;

        // ---- S = Q K^T (hi-only, 64 MMAs) ----
        float s[8][4];
#pragma unroll
        for (int nt = 0; nt < 8; nt++)
#pragma unroll
            for (int q = 0; q < 4; q++) s[nt][q] = 0.f;
#pragma unroll
        for (int kt = 0; kt < 8; kt++) {
            uint32_t bh_[4][4];
#pragma unroll
            for (int ng = 0; ng < 4; ng++) {
                uint32_t ro = (uint32_t)(ng * 16 + (grp >> 1) * 8 + r8) * AT_PITCH
                            + kt * 32 + (grp & 1) * 16;
                ldsm4(bh_[ng], stb + AT_KH + ro);
            }
#pragma unroll
            for (int ng = 0; ng < 4; ng++)
#pragma unroll
                for (int hf = 0; hf < 2; hf++)
                    mma_bf16(s[ng * 2 + hf], qfh[kt], &bh_[ng][hf * 2]);
        }

        // ---- d = l + l^2/2, l = silu(s)/N, masked ----
#pragma unroll
        for (int hf = 0; hf < 2; hf++) {
            int rloc = w * 16 + quad + hf * 8;
            int n = n0 + rloc;
            int validn = vn[rloc];
            float psum = 0.f;
#pragma unroll
            for (int nt = 0; nt < 8; nt++)
#pragma unroll
                for (int c2 = 0; c2 < 2; c2++) {
                    int mloc = nt * 8 + tq * 2 + c2;
                    int m = m0 + mloc;
                    bool cc = (m > n) && validn && vm[mloc];
                    float sc = s[nt][hf * 2 + c2];
                    float l = __fdividef(sc, 1.f + __expf(-sc)) * INV_N;
                    float d = cc ? fmaf(0.5f * l, l, l) : 0.f;
                    s[nt][hf * 2 + c2] = d;
                    psum += d;
                }
            psum += __shfl_xor_sync(0xffffffffu, psum, 1);
            psum += __shfl_xor_sync(0xffffffffu, psum, 2);
            run_l[hf] += psum;
        }

        // ---- O += D V (D split hi/lo in regs; V hi via ldmatrix.trans) ----
#pragma unroll
        for (int kv = 0; kv < 4; kv++) {
            uint32_t dh[4], dl[4];
#pragma unroll
            for (int half = 0; half < 2; half++) {
                int nt = kv * 2 + half;
                bf16 h0, l0, h1, l1, h2, l2, h3, l3;
                split2(s[nt][0], h0, l0); split2(s[nt][1], h1, l1);
                split2(s[nt][2], h2, l2); split2(s[nt][3], h3, l3);
                dh[half * 2 + 0] = pkbf(h0, h1);  dl[half * 2 + 0] = pkbf(l0, l1);
                dh[half * 2 + 1] = pkbf(h2, h3);  dl[half * 2 + 1] = pkbf(l2, l3);
            }
#pragma unroll
            for (int dg = 0; dg < 8; dg++) {
                uint32_t vfh[4];
                uint32_t ro = (uint32_t)(kv * 16 + (grp & 1) * 8 + r8) * AT_PITCH
                            + dg * 32 + (grp >> 1) * 16;
                ldsm4t(vfh, stb + AT_VH + ro);
#pragma unroll
                for (int hf = 0; hf < 2; hf++) {
                    int dt = dg * 2 + hf;
                    mma_bf16(o[dt], dh, &vfh[hf * 2]);
                    mma_bf16(o[dt], dl, &vfh[hf * 2]);
                }
            }
        }
        __syncthreads();
    }

    // ---- epilogue: O = (SUF + O_dev) / (CNT + sum_d), fallback -> meanV ----
#pragma unroll
    for (int hf = 0; hf < 2; hf++) {
        int rloc = w * 16 + quad + hf * 8;
        int n = n0 + rloc;
        int validn = vn[rloc];
        float cnt = g_cnt[bh * NN + n];
        bool fb = (!validn) || (cnt < 0.5f);
        float inv = fb ? 0.f : 1.f / (cnt + run_l[hf]);
        const float* sufp = g_suf + ((size_t)bh * NN + n) * 128;
        const float* mvp = g_mv + bh * 128;
        size_t orow = (size_t)(b * NN + n) * DD + h * 128;
#pragma unroll
        for (int dt = 0; dt < 16; dt++) {
            int d = dt * 8 + tq * 2;
            float x0, x1;
            if (fb) { x0 = mvp[d]; x1 = mvp[d + 1]; }
            else {
                float2 sv = *(const float2*)&sufp[d];
                x0 = (sv.x + o[dt][hf * 2 + 0]) * inv;
                x1 = (sv.y + o[dt][hf * 2 + 1]) * inv;
            }
            bf16 h0, l0, h1, l1;
            split2(x0, h0, l0); split2(x1, h1, l1);
            ushort2 hv = {us(h0), us(h1)};
            ushort2 lv = {us(l0), us(l1)};
            *(ushort2*)&g_ath[orow + d] = hv;
            *(ushort2*)&g_atl[orow + d] = lv;
        }
    }
}

// ---------------- launch ----------------
extern "C" void kernel_launch(void* const* d_in, const int* in_sizes, int n_in,
                              void* d_out, int out_size) {
    const int*   ids  = (const int*)d_in[1];     // past_ids (B,N)
    const float* emb  = (const float*)d_in[2];   // past_embeddings (B,N,D)
    const float* qkvw = (const float*)d_in[3];   // (4,1024,4096)
    const float* qkvb = (const float*)d_in[4];   // (4,4096)
    const float* outw = (const float*)d_in[5];   // (4,1024,1024)
    const float* outb = (const float*)d_in[6];   // (4,1024)
    const float* lng  = (const float*)d_in[7];   // (4,1024)
    const float* lnb  = (const float*)d_in[8];   // (4,1024)
    float* X = (float*)d_out;

    cudaFuncSetAttribute(attn_kernel,
                         cudaFuncAttributeMaxDynamicSharedMemorySize, ATTN_SMEM);
    cudaFuncSetAttribute(hmma_gemm,
                         cudaFuncAttributeMaxDynamicSharedMemorySize, HM_SMEM);

    cudaMemcpyAsync(X, emb, sizeof(float) * (size_t)MM * DD,
                    cudaMemcpyDeviceToDevice);

    wq_cvt<<<dim3(32, 96, NBLK), dim3(32, 8)>>>(qkvw);
    w2_cvt<<<dim3(32, 32, NBLK), dim3(32, 8)>>>(outw);

    for (int l = 0; l < NBLK; l++) {
        ln_kernel<<<MM, 256>>>(X, lng + l * DD, lnb + l * DD);
        hmma_gemm<<<dim3(24, 64), 256, HM_SMEM>>>(0, l, qkvb + (size_t)l * QKVW, X);
        sufA<<<dim3(NCK, BB * HH), 128>>>(ids);
        sufB<<<dim3(NCK, BB * HH), 128>>>();
        attn_kernel<<<dim3(NN / 128, HH, BB), 256, ATTN_SMEM>>>(ids);
        hmma_gemm<<<dim3(8, 64), 256, HM_SMEM>>>(1, l, outb + (size_t)l * DD, X);
    }
}

// round 13
// speedup vs baseline: 1.5662x; 1.5662x over previous
#include <cuda_runtime.h>
#include <cuda_bf16.h>
#include <math.h>
#include <stdint.h>

#define BB 4
#define NN 2048
#define DD 1024
#define HH 8
#define NBLK 4
#define MM (BB*NN)          // 8192 rows
#define QKVW 4096
#define QSCALE 0.08838834764831845f   // 1/sqrt(128)
#define INV_N (1.0f/2048.0f)
#define NCK 8
#define CKR (NN/NCK)        // 256

typedef __nv_bfloat16 bf16;

// ---------------- scratch (device globals; no allocation allowed) ----------
__device__ bf16  g_xnh[MM*DD];           // ln output hi
__device__ bf16  g_xnl[MM*DD];           // ln output lo
__device__ bf16  g_qh[BB*HH*NN*128];     // q (scaled) bf16   [b,h,n,d]
__device__ bf16  g_kh[BB*HH*NN*128];     // k bf16
__device__ bf16  g_vh[BB*HH*NN*128];     // v hi
__device__ bf16  g_vl[BB*HH*NN*128];     // v lo
__device__ bf16  g_ath[MM*DD];           // attn output hi
__device__ bf16  g_atl[MM*DD];           // attn output lo
__device__ float g_mv [BB*HH*128];       // fallback: mean over ALL keys of v
__device__ float g_suf[(size_t)BB*HH*NN*128];  // 32 MB suffix sums
__device__ float g_cnt[BB*HH*NN];
__device__ float g_ctv[BB*HH*NCK*128];   // valid-gated chunk totals
__device__ float g_ctu[BB*HH*NCK*128];   // ungated chunk totals
__device__ float g_ckc[BB*HH*NCK];
__device__ bf16  g_wqh[(size_t)NBLK*3072*DD];  // qkv W^T hi  [l][n(3072)][k]
__device__ bf16  g_wql[(size_t)NBLK*3072*DD];
__device__ bf16  g_w2h[(size_t)NBLK*DD*DD];    // out W^T hi
__device__ bf16  g_w2l[(size_t)NBLK*DD*DD];

// ---------------- small helpers ----------------
__device__ __forceinline__ void split2(float x, bf16 &h, bf16 &l) {
    h = __float2bfloat16(x);
    l = __float2bfloat16(x - __bfloat162float(h));
}
__device__ __forceinline__ unsigned short us(bf16 h) { return __bfloat16_as_ushort(h); }
__device__ __forceinline__ uint32_t pkbf(bf16 lo, bf16 hi) {
    return ((uint32_t)us(hi) << 16) | us(lo);
}

// ---------------- HMMA path: mma.sync + ldmatrix + cp.async ---------------
__device__ __forceinline__ uint32_t smem_u32(const void* p) {
    uint32_t a;
    asm("{ .reg .u64 t; cvta.to.shared.u64 t, %1; cvt.u32.u64 %0, t; }"
        : "=r"(a) : "l"(p));
    return a;
}
__device__ __forceinline__ void mma_bf16(float* c, const uint32_t* a, const uint32_t* b) {
    asm volatile(
        "mma.sync.aligned.m16n8k16.row.col.f32.bf16.bf16.f32 "
        "{%0,%1,%2,%3}, {%4,%5,%6,%7}, {%8,%9}, {%0,%1,%2,%3};"
        : "+f"(c[0]), "+f"(c[1]), "+f"(c[2]), "+f"(c[3])
        : "r"(a[0]), "r"(a[1]), "r"(a[2]), "r"(a[3]), "r"(b[0]), "r"(b[1]));
}
__device__ __forceinline__ void ldsm4(uint32_t* r, uint32_t addr) {
    asm volatile("ldmatrix.sync.aligned.m8n8.x4.shared.b16 {%0,%1,%2,%3}, [%4];"
                 : "=r"(r[0]), "=r"(r[1]), "=r"(r[2]), "=r"(r[3]) : "r"(addr));
}
__device__ __forceinline__ void ldsm4t(uint32_t* r, uint32_t addr) {
    asm volatile("ldmatrix.sync.aligned.m8n8.x4.trans.shared.b16 {%0,%1,%2,%3}, [%4];"
                 : "=r"(r[0]), "=r"(r[1]), "=r"(r[2]), "=r"(r[3]) : "r"(addr));
}
__device__ __forceinline__ void cpa16(uint32_t dst, const void* src) {
    asm volatile("cp.async.ca.shared.global [%0], [%1], 16;"
                 :: "r"(dst), "l"(src) : "memory");
}
#define CPA_COMMIT asm volatile("cp.async.commit_group;" ::: "memory")
#define CPA_WAIT1  asm volatile("cp.async.wait_group 1;" ::: "memory")
#define CPA_WAIT0  asm volatile("cp.async.wait_group 0;" ::: "memory")

// ---------------- LayerNorm: one row per block, emits bf16 hi/lo ----------
__global__ void ln_kernel(const float* __restrict__ x,
                          const float* __restrict__ g,
                          const float* __restrict__ bta) {
    __shared__ float sh[8];
    __shared__ float bc[2];
    int row = blockIdx.x;
    int tid = threadIdx.x;
    int lane = tid & 31, wid = tid >> 5;

    const float4* xr = (const float4*)(x + (size_t)row * DD);
    float4 v = xr[tid];

    float s = v.x + v.y + v.z + v.w;
#pragma unroll
    for (int o = 16; o > 0; o >>= 1) s += __shfl_xor_sync(0xffffffffu, s, o);
    if (lane == 0) sh[wid] = s;
    __syncthreads();
    if (tid == 0) {
        float t = 0.f;
#pragma unroll
        for (int i = 0; i < 8; i++) t += sh[i];
        bc[0] = t;
    }
    __syncthreads();
    float mu = bc[0] * (1.f / DD);

    float dx = v.x - mu, dy = v.y - mu, dz = v.z - mu, dw = v.w - mu;

    float sq = dx*dx + dy*dy + dz*dz + dw*dw;
#pragma unroll
    for (int o = 16; o > 0; o >>= 1) sq += __shfl_xor_sync(0xffffffffu, sq, o);
    if (lane == 0) sh[wid] = sq;
    __syncthreads();
    if (tid == 0) {
        float t = 0.f;
#pragma unroll
        for (int i = 0; i < 8; i++) t += sh[i];
        bc[1] = t;
    }
    __syncthreads();
    float rs = rsqrtf(bc[1] * (1.f / DD) + 1e-5f);

    float4 gg = ((const float4*)g)[tid];
    float4 bb = ((const float4*)bta)[tid];
    float o0 = dx * rs * gg.x + bb.x;
    float o1 = dy * rs * gg.y + bb.y;
    float o2 = dz * rs * gg.z + bb.z;
    float o3 = dw * rs * gg.w + bb.w;

    bf16 h0, h1, h2, h3, l0, l1, l2, l3;
    split2(o0, h0, l0); split2(o1, h1, l1);
    split2(o2, h2, l2); split2(o3, h3, l3);
    size_t o = (size_t)row * DD + tid * 4;
    ushort4 hv = {us(h0), us(h1), us(h2), us(h3)};
    ushort4 lv = {us(l0), us(l1), us(l2), us(l3)};
    *(ushort4*)&g_xnh[o] = hv;
    *(ushort4*)&g_xnl[o] = lv;
}

// ---------------- weight transpose + split (once per launch) ---------------
__global__ void wq_cvt(const float* __restrict__ qkvw) {
    __shared__ float t[32][33];
    int l = blockIdx.z;
    int k0 = blockIdx.x * 32, n0 = blockIdx.y * 32;
    int chunk = n0 >> 7, head = chunk / 3, part = chunk % 3;
    int wbase = head * 512 + part * 128 + (n0 & 127);
    const float* W = qkvw + (size_t)l * DD * QKVW;
#pragma unroll
    for (int s = 0; s < 4; s++)
        t[threadIdx.y + 8*s][threadIdx.x] =
            W[(size_t)(k0 + threadIdx.y + 8*s) * QKVW + wbase + threadIdx.x];
    __syncthreads();
#pragma unroll
    for (int s = 0; s < 4; s++) {
        int n = n0 + threadIdx.y + 8*s;
        float v = t[threadIdx.x][threadIdx.y + 8*s];
        bf16 h, lo; split2(v, h, lo);
        size_t o = ((size_t)l * 3072 + n) * DD + k0 + threadIdx.x;
        g_wqh[o] = h; g_wql[o] = lo;
    }
}
__global__ void w2_cvt(const float* __restrict__ outw) {
    __shared__ float t[32][33];
    int l = blockIdx.z;
    int k0 = blockIdx.x * 32, n0 = blockIdx.y * 32;
    const float* W = outw + (size_t)l * DD * DD;
#pragma unroll
    for (int s = 0; s < 4; s++)
        t[threadIdx.y + 8*s][threadIdx.x] =
            W[(size_t)(k0 + threadIdx.y + 8*s) * DD + n0 + threadIdx.x];
    __syncthreads();
#pragma unroll
    for (int s = 0; s < 4; s++) {
        int n = n0 + threadIdx.y + 8*s;
        float v = t[threadIdx.x][threadIdx.y + 8*s];
        bf16 h, lo; split2(v, h, lo);
        size_t o = ((size_t)l * DD + n) * DD + k0 + threadIdx.x;
        g_w2h[o] = h; g_w2l[o] = lo;
    }
}

// ---------------- HMMA GEMM: 128x128 tile, BK=32, UNIFORM 3-MMA split -----
// mode 0: C = xn @ Wqkv + bias -> q/k hi-only bf16, v split   (grid (24, 64))
// mode 1: X += attn @ Wout + bias                             (grid (8, 64))
#define RSTR 80
#define ST_A_H 0
#define ST_A_L 10240
#define ST_B_H 20480
#define ST_B_L 30720
#define STAGE  40960
#define HM_SMEM (2*STAGE)

__global__ __launch_bounds__(256) void hmma_gemm(int mode, int layer,
                                                 const float* __restrict__ bias,
                                                 float* __restrict__ X) {
    extern __shared__ char smem[];
    uint32_t sb = smem_u32(smem);
    int tid = threadIdx.x;
    int w = tid >> 5, lane = tid & 31;
    int row0 = blockIdx.y * 128;
    int bx = blockIdx.x;

    const bf16* Ah = ((mode == 0) ? g_xnh : g_ath) + (size_t)row0 * DD;
    const bf16* Al = ((mode == 0) ? g_xnl : g_atl) + (size_t)row0 * DD;
    const bf16* Bh = ((mode == 0) ? (g_wqh + (size_t)layer * 3072 * DD)
                                  : (g_w2h + (size_t)layer * DD * DD))
                     + (size_t)(bx * 128) * DD;
    const bf16* Bl = ((mode == 0) ? (g_wql + (size_t)layer * 3072 * DD)
                                  : (g_w2l + (size_t)layer * DD * DD))
                     + (size_t)(bx * 128) * DD;

    float c[4][4][4];
#pragma unroll
    for (int i = 0; i < 4; i++)
#pragma unroll
        for (int j = 0; j < 4; j++)
#pragma unroll
            for (int q = 0; q < 4; q++) c[i][j][q] = 0.f;

    int wm = w & 1, wn = w >> 1;
    int grp = lane >> 3, r8 = lane & 7;
    int arow = wm * 64 + (grp & 1) * 8 + r8;
    int akb0 = (grp >> 1) * 16;
    int brow = wn * 32 + (grp >> 1) * 8 + r8;
    int bkb0 = (grp & 1) * 16;

    {
        uint32_t s0 = sb;
#pragma unroll
        for (int ch = tid; ch < 512; ch += 256) {
            int row = ch >> 2, cw = ch & 3;
            uint32_t so = row * RSTR + cw * 16;
            size_t go = (size_t)row * DD + cw * 8;
            cpa16(s0 + ST_A_H + so, (const char*)(Ah + go));
            cpa16(s0 + ST_A_L + so, (const char*)(Al + go));
            cpa16(s0 + ST_B_H + so, (const char*)(Bh + go));
            cpa16(s0 + ST_B_L + so, (const char*)(Bl + go));
        }
        CPA_COMMIT;
    }

    for (int s = 0; s < 32; s++) {
        if (s + 1 < 32) {
            uint32_t s0 = sb + ((s + 1) & 1) * STAGE;
            int k0 = (s + 1) * 32;
#pragma unroll
            for (int ch = tid; ch < 512; ch += 256) {
                int row = ch >> 2, cw = ch & 3;
                uint32_t so = row * RSTR + cw * 16;
                size_t go = (size_t)row * DD + k0 + cw * 8;
                cpa16(s0 + ST_A_H + so, (const char*)(Ah + go));
                cpa16(s0 + ST_A_L + so, (const char*)(Al + go));
                cpa16(s0 + ST_B_H + so, (const char*)(Bh + go));
                cpa16(s0 + ST_B_L + so, (const char*)(Bl + go));
            }
        }
        CPA_COMMIT;
        CPA_WAIT1;
        __syncthreads();
        uint32_t base = sb + (s & 1) * STAGE;
#pragma unroll
        for (int k16 = 0; k16 < 2; k16++) {
            uint32_t ah[4][4], al[4][4], bh[2][4], bl[2][4];
            int akb = k16 * 32 + akb0;
            int bkb = k16 * 32 + bkb0;
#pragma unroll
            for (int i = 0; i < 4; i++) {
                uint32_t ao = (uint32_t)(arow + i * 16) * RSTR + akb;
                ldsm4(ah[i], base + ST_A_H + ao);
                ldsm4(al[i], base + ST_A_L + ao);
            }
#pragma unroll
            for (int j = 0; j < 2; j++) {
                uint32_t bo = (uint32_t)(brow + j * 16) * RSTR + bkb;
                ldsm4(bh[j], base + ST_B_H + bo);
                ldsm4(bl[j], base + ST_B_L + bo);
            }
#pragma unroll
            for (int i = 0; i < 4; i++)
#pragma unroll
                for (int jn = 0; jn < 4; jn++) {
                    const uint32_t* bph = &bh[jn >> 1][(jn & 1) * 2];
                    const uint32_t* bpl = &bl[jn >> 1][(jn & 1) * 2];
                    mma_bf16(c[i][jn], ah[i], bph);
                    mma_bf16(c[i][jn], ah[i], bpl);
                    mma_bf16(c[i][jn], al[i], bph);
                }
        }
        __syncthreads();
    }
    CPA_WAIT0;

    int quad = lane >> 2, tq = lane & 3;
    if (mode == 0) {
        int head = bx / 3, part = bx % 3;
        int wcol0 = head * 512 + part * 128;
        bf16* dh = (part == 0) ? g_qh : (part == 1) ? g_kh : g_vh;
        float scale = (part == 0) ? QSCALE : 1.f;
#pragma unroll
        for (int i = 0; i < 4; i++)
#pragma unroll
            for (int half = 0; half < 2; half++) {
                int r = row0 + wm * 64 + i * 16 + quad + half * 8;
                int b = r >> 11, n = r & (NN - 1);
                size_t ro = ((size_t)(b * HH + head) * NN + n) * 128;
#pragma unroll
                for (int jn = 0; jn < 4; jn++) {
                    int col = wn * 32 + jn * 8 + tq * 2;
                    float x0 = (c[i][jn][half*2+0] + bias[wcol0 + col]) * scale;
                    float x1 = (c[i][jn][half*2+1] + bias[wcol0 + col + 1]) * scale;
                    if (part == 2) {
                        bf16 h0, l0, h1, l1;
                        split2(x0, h0, l0); split2(x1, h1, l1);
                        ushort2 hv = {us(h0), us(h1)};
                        ushort2 lv = {us(l0), us(l1)};
                        *(ushort2*)&dh[ro + col] = hv;
                        *(ushort2*)&g_vl[ro + col] = lv;
                    } else {
                        ushort2 hv = {us(__float2bfloat16(x0)),
                                      us(__float2bfloat16(x1))};
                        *(ushort2*)&dh[ro + col] = hv;
                    }
                }
            }
    } else {
        int col0 = bx * 128;
#pragma unroll
        for (int i = 0; i < 4; i++)
#pragma unroll
            for (int half = 0; half < 2; half++) {
                size_t r = row0 + wm * 64 + i * 16 + quad + half * 8;
#pragma unroll
                for (int jn = 0; jn < 4; jn++) {
                    int col = col0 + wn * 32 + jn * 8 + tq * 2;
                    float2 x = *(float2*)&X[r * DD + col];
                    x.x += c[i][jn][half*2+0] + bias[col];
                    x.y += c[i][jn][half*2+1] + bias[col + 1];
                    *(float2*)&X[r * DD + col] = x;
                }
            }
    }
}

// ---------------- suffix sums of V (chunked 2-pass) ------------------------
__global__ void sufA(const int* __restrict__ ids) {   // grid (NCK, 32), 128
    int ck = blockIdx.x, bh = blockIdx.y, b = bh >> 3;
    int d = threadIdx.x;
    size_t vbase = (size_t)bh * NN * 128 + d;
    int m0 = ck * CKR;
    float suf = 0.f, tot = 0.f, cnt = 0.f;
    for (int m = m0 + CKR - 1; m >= m0; m--) {
        float v = __bfloat162float(g_vh[vbase + (size_t)m * 128])
                + __bfloat162float(g_vl[vbase + (size_t)m * 128]);
        g_suf[((size_t)bh * NN + m) * 128 + d] = suf;
        if (d == 0) g_cnt[bh * NN + m] = cnt;
        tot += v;
        if (ids[b * NN + m] != 0) { suf += v; cnt += 1.f; }
    }
    g_ctv[(bh * NCK + ck) * 128 + d] = suf;
    g_ctu[(bh * NCK + ck) * 128 + d] = tot;
    if (d == 0) g_ckc[bh * NCK + ck] = cnt;
}
__global__ void sufB() {                              // grid (NCK, 32), 128
    int ck = blockIdx.x, bh = blockIdx.y;
    int d = threadIdx.x;
    float offs = 0.f, offc = 0.f;
    for (int cc = ck + 1; cc < NCK; cc++) {
        offs += g_ctv[(bh * NCK + cc) * 128 + d];
        offc += g_ckc[bh * NCK + cc];
    }
    if (ck == 0) {
        float t = 0.f;
        for (int cc = 0; cc < NCK; cc++) t += g_ctu[(bh * NCK + cc) * 128 + d];
        g_mv[bh * 128 + d] = t * INV_N;
    }
    int m0 = ck * CKR;
    if (ck < NCK - 1)
        for (int m = m0; m < m0 + CKR; m++) {
            g_suf[((size_t)bh * NN + m) * 128 + d] += offs;
            if (d == 0) g_cnt[bh * NN + m] += offc;
        }
}

// ---------------- attention: HMMA flash, 128-q CTA, 64-key tiles ----------
// p = exp(silu(s)/N) = 1 + d, d = l + l^2/2 (|l| < 3e-3 => Taylor exact).
// Mask part from SUF/CNT; kernel computes S = Q K^T and D.V, both hi-only
// bf16 (D.V is a ~0.1-1% correction term; bf16 error on it is ~1e-5 total).
#define AT_PITCH 272
#define AT_KH 0
#define AT_VH 17408
#define AT_STAGE 34816
#define AT_FLAGS (2*AT_STAGE)
#define ATTN_SMEM (AT_FLAGS + 512 + 512)

__global__ __launch_bounds__(256) void attn_kernel(const int* __restrict__ ids) {
    extern __shared__ char smem[];
    uint32_t sb = smem_u32(smem);
    int* vn  = (int*)(smem + AT_FLAGS);
    int* vmb = (int*)(smem + AT_FLAGS + 512);

    int tid = threadIdx.x;
    int w = tid >> 5, lane = tid & 31;
    int quad = lane >> 2, tq = lane & 3;
    int grp = lane >> 3, r8 = lane & 7;
    int n0 = blockIdx.x * 128;
    int h = blockIdx.y, b = blockIdx.z;
    int bh = b * HH + h;
    size_t base = (size_t)bh * NN * 128;

    // ---- stage Q (hi) into stage area, pull fragments to regs ----
    {
        const char* ph = (const char*)(g_qh + base + (size_t)n0 * 128);
        for (int ch = tid; ch < 2048; ch += 256) {
            int row = ch >> 4, c = ch & 15;
            cpa16(sb + row * AT_PITCH + c * 16, ph + row * 256 + c * 16);
        }
        CPA_COMMIT; CPA_WAIT0;
    }
    if (tid < 128) vn[tid] = (ids[b * NN + n0 + tid] != 0);
    __syncthreads();

    uint32_t qfh[8][4];
    {
        int arow = w * 16 + (grp & 1) * 8 + r8;
#pragma unroll
        for (int kt = 0; kt < 8; kt++) {
            uint32_t ao = (uint32_t)arow * AT_PITCH + kt * 32 + (grp >> 1) * 16;
            ldsm4(qfh[kt], sb + ao);
        }
    }
    __syncthreads();

    float o[16][4];
#pragma unroll
    for (int dt = 0; dt < 16; dt++)
#pragma unroll
        for (int q = 0; q < 4; q++) o[dt][q] = 0.f;
    float run_l[2] = {0.f, 0.f};

    const char* kh = (const char*)(g_kh + base);
    const char* vh = (const char*)(g_vh + base);

    int mt0 = n0 >> 6;
    auto prefetch = [&](int mt, int st) {
        int m0 = mt * 64;
        uint32_t s0 = sb + st * AT_STAGE;
        for (int ch = tid; ch < 1024; ch += 256) {
            int row = ch >> 4, c = ch & 15;
            uint32_t so = row * AT_PITCH + c * 16;
            size_t go = (size_t)(m0 + row) * 256 + c * 16;
            cpa16(s0 + AT_KH + so, kh + go);
            cpa16(s0 + AT_VH + so, vh + go);
        }
        if (tid < 64) vmb[st * 64 + tid] = (ids[b * NN + m0 + tid] != 0);
        CPA_COMMIT;
    };
    prefetch(mt0, 0);

    for (int mt = mt0; mt < NN / 64; mt++) {
        int st = (mt - mt0) & 1;
        if (mt + 1 < NN / 64) { prefetch(mt + 1, st ^ 1); CPA_WAIT1; }
        else                  { CPA_WAIT0; }
        __syncthreads();

        uint32_t stb = sb + st * AT_STAGE;
        int m0 = mt * 64;
        const int* vm = vmb + st * 64;

        // ---- S = Q K^T (hi-only, 64 MMAs) ----
        float s[8][4];
#pragma unroll
        for (int nt = 0; nt < 8; nt++)
#pragma unroll
            for (int q = 0; q < 4; q++) s[nt][q] = 0.f;
#pragma unroll
        for (int kt = 0; kt < 8; kt++) {
            uint32_t bh_[4][4];
#pragma unroll
            for (int ng = 0; ng < 4; ng++) {
                uint32_t ro = (uint32_t)(ng * 16 + (grp >> 1) * 8 + r8) * AT_PITCH
                            + kt * 32 + (grp & 1) * 16;
                ldsm4(bh_[ng], stb + AT_KH + ro);
            }
#pragma unroll
            for (int ng = 0; ng < 4; ng++)
#pragma unroll
                for (int hf = 0; hf < 2; hf++)
                    mma_bf16(s[ng * 2 + hf], qfh[kt], &bh_[ng][hf * 2]);
        }

        // ---- d = l + l^2/2, l = silu(s)/N, masked ----
#pragma unroll
        for (int hf = 0; hf < 2; hf++) {
            int rloc = w * 16 + quad + hf * 8;
            int n = n0 + rloc;
            int validn = vn[rloc];
            float psum = 0.f;
#pragma unroll
            for (int nt = 0; nt < 8; nt++)
#pragma unroll
                for (int c2 = 0; c2 < 2; c2++) {
                    int mloc = nt * 8 + tq * 2 + c2;
                    int m = m0 + mloc;
                    bool cc = (m > n) && validn && vm[mloc];
                    float sc = s[nt][hf * 2 + c2];
                    float l = __fdividef(sc, 1.f + __expf(-sc)) * INV_N;
                    float d = cc ? fmaf(0.5f * l, l, l) : 0.f;
                    s[nt][hf * 2 + c2] = d;
                    psum += d;
                }
            psum += __shfl_xor_sync(0xffffffffu, psum, 1);
            psum += __shfl_xor_sync(0xffffffffu, psum, 2);
            run_l[hf] += psum;
        }

        // ---- O += D V (D bf16 hi-only; V hi via ldmatrix.trans; 64 MMAs) --
#pragma unroll
        for (int kv = 0; kv < 4; kv++) {
            uint32_t dh[4];
#pragma unroll
            for (int half = 0; half < 2; half++) {
                int nt = kv * 2 + half;
                bf16 h0 = __float2bfloat16(s[nt][0]);
                bf16 h1 = __float2bfloat16(s[nt][1]);
                bf16 h2 = __float2bfloat16(s[nt][2]);
                bf16 h3 = __float2bfloat16(s[nt][3]);
                dh[half * 2 + 0] = pkbf(h0, h1);
                dh[half * 2 + 1] = pkbf(h2, h3);
            }
#pragma unroll
            for (int dg = 0; dg < 8; dg++) {
                uint32_t vfh[4];
                uint32_t ro = (uint32_t)(kv * 16 + (grp & 1) * 8 + r8) * AT_PITCH
                            + dg * 32 + (grp >> 1) * 16;
                ldsm4t(vfh, stb + AT_VH + ro);
#pragma unroll
                for (int hf = 0; hf < 2; hf++)
                    mma_bf16(o[dg * 2 + hf], dh, &vfh[hf * 2]);
            }
        }
        __syncthreads();
    }

    // ---- epilogue: O = (SUF + O_dev) / (CNT + sum_d), fallback -> meanV ----
#pragma unroll
    for (int hf = 0; hf < 2; hf++) {
        int rloc = w * 16 + quad + hf * 8;
        int n = n0 + rloc;
        int validn = vn[rloc];
        float cnt = g_cnt[bh * NN + n];
        bool fb = (!validn) || (cnt < 0.5f);
        float inv = fb ? 0.f : 1.f / (cnt + run_l[hf]);
        const float* sufp = g_suf + ((size_t)bh * NN + n) * 128;
        const float* mvp = g_mv + bh * 128;
        size_t orow = (size_t)(b * NN + n) * DD + h * 128;
#pragma unroll
        for (int dt = 0; dt < 16; dt++) {
            int d = dt * 8 + tq * 2;
            float x0, x1;
            if (fb) { x0 = mvp[d]; x1 = mvp[d + 1]; }
            else {
                float2 sv = *(const float2*)&sufp[d];
                x0 = (sv.x + o[dt][hf * 2 + 0]) * inv;
                x1 = (sv.y + o[dt][hf * 2 + 1]) * inv;
            }
            bf16 h0, l0, h1, l1;
            split2(x0, h0, l0); split2(x1, h1, l1);
            ushort2 hv = {us(h0), us(h1)};
            ushort2 lv = {us(l0), us(l1)};
            *(ushort2*)&g_ath[orow + d] = hv;
            *(ushort2*)&g_atl[orow + d] = lv;
        }
    }
}

// ---------------- launch ----------------
extern "C" void kernel_launch(void* const* d_in, const int* in_sizes, int n_in,
                              void* d_out, int out_size) {
    const int*   ids  = (const int*)d_in[1];     // past_ids (B,N)
    const float* emb  = (const float*)d_in[2];   // past_embeddings (B,N,D)
    const float* qkvw = (const float*)d_in[3];   // (4,1024,4096)
    const float* qkvb = (const float*)d_in[4];   // (4,4096)
    const float* outw = (const float*)d_in[5];   // (4,1024,1024)
    const float* outb = (const float*)d_in[6];   // (4,1024)
    const float* lng  = (const float*)d_in[7];   // (4,1024)
    const float* lnb  = (const float*)d_in[8];   // (4,1024)
    float* X = (float*)d_out;

    cudaFuncSetAttribute(attn_kernel,
                         cudaFuncAttributeMaxDynamicSharedMemorySize, ATTN_SMEM);
    cudaFuncSetAttribute(hmma_gemm,
                         cudaFuncAttributeMaxDynamicSharedMemorySize, HM_SMEM);

    cudaMemcpyAsync(X, emb, sizeof(float) * (size_t)MM * DD,
                    cudaMemcpyDeviceToDevice);

    wq_cvt<<<dim3(32, 96, NBLK), dim3(32, 8)>>>(qkvw);
    w2_cvt<<<dim3(32, 32, NBLK), dim3(32, 8)>>>(outw);

    for (int l = 0; l < NBLK; l++) {
        ln_kernel<<<MM, 256>>>(X, lng + l * DD, lnb + l * DD);
        hmma_gemm<<<dim3(24, 64), 256, HM_SMEM>>>(0, l, qkvb + (size_t)l * QKVW, X);
        sufA<<<dim3(NCK, BB * HH), 128>>>(ids);
        sufB<<<dim3(NCK, BB * HH), 128>>>();
        attn_kernel<<<dim3(NN / 128, HH, BB), 256, ATTN_SMEM>>>(ids);
        hmma_gemm<<<dim3(8, 64), 256, HM_SMEM>>>(1, l, outb + (size_t)l * DD, X);
    }
}

// round 14
// speedup vs baseline: 1.8515x; 1.1821x over previous
#include <cuda_runtime.h>
#include <cuda_bf16.h>
#include <math.h>
#include <stdint.h>

#define BB 4
#define NN 2048
#define DD 1024
#define HH 8
#define NBLK 4
#define MM (BB*NN)          // 8192 rows
#define QKVW 4096
#define QSCALE 0.08838834764831845f   // 1/sqrt(128)
#define INV_N (1.0f/2048.0f)
#define NCK 8
#define CKR (NN/NCK)        // 256

typedef __nv_bfloat16 bf16;

// ---------------- scratch (device globals; no allocation allowed) ----------
__device__ bf16  g_xnh[MM*DD];           // ln output hi
__device__ bf16  g_xnl[MM*DD];           // ln output lo
__device__ bf16  g_qh[BB*HH*NN*128];     // q (scaled) bf16   [b,h,n,d]
__device__ bf16  g_kh[BB*HH*NN*128];     // k bf16
__device__ bf16  g_vh[BB*HH*NN*128];     // v hi
__device__ bf16  g_vl[BB*HH*NN*128];     // v lo
__device__ bf16  g_ath[MM*DD];           // attn output hi
__device__ bf16  g_atl[MM*DD];           // attn output lo
__device__ float g_mv [BB*HH*128];       // fallback: mean over ALL keys of v
__device__ float g_suf[(size_t)BB*HH*NN*128];  // 32 MB suffix sums
__device__ float g_cnt[BB*HH*NN];
__device__ float g_ctv[BB*HH*NCK*128];   // valid-gated chunk totals
__device__ float g_ctu[BB*HH*NCK*128];   // ungated chunk totals
__device__ float g_ckc[BB*HH*NCK];
__device__ bf16  g_wqh[(size_t)NBLK*3072*DD];  // qkv W^T hi  [l][n(3072)][k]
__device__ bf16  g_wql[(size_t)NBLK*3072*DD];
__device__ bf16  g_w2h[(size_t)NBLK*DD*DD];    // out W^T hi
__device__ bf16  g_w2l[(size_t)NBLK*DD*DD];

// ---------------- small helpers ----------------
__device__ __forceinline__ void split2(float x, bf16 &h, bf16 &l) {
    h = __float2bfloat16(x);
    l = __float2bfloat16(x - __bfloat162float(h));
}
__device__ __forceinline__ unsigned short us(bf16 h) { return __bfloat16_as_ushort(h); }
__device__ __forceinline__ uint32_t pkbf(bf16 lo, bf16 hi) {
    return ((uint32_t)us(hi) << 16) | us(lo);
}

// ---------------- HMMA path: mma.sync + ldmatrix + cp.async ---------------
__device__ __forceinline__ uint32_t smem_u32(const void* p) {
    uint32_t a;
    asm("{ .reg .u64 t; cvta.to.shared.u64 t, %1; cvt.u32.u64 %0, t; }"
        : "=r"(a) : "l"(p));
    return a;
}
__device__ __forceinline__ void mma_bf16(float* c, const uint32_t* a, const uint32_t* b) {
    asm volatile(
        "mma.sync.aligned.m16n8k16.row.col.f32.bf16.bf16.f32 "
        "{%0,%1,%2,%3}, {%4,%5,%6,%7}, {%8,%9}, {%0,%1,%2,%3};"
        : "+f"(c[0]), "+f"(c[1]), "+f"(c[2]), "+f"(c[3])
        : "r"(a[0]), "r"(a[1]), "r"(a[2]), "r"(a[3]), "r"(b[0]), "r"(b[1]));
}
__device__ __forceinline__ void ldsm4(uint32_t* r, uint32_t addr) {
    asm volatile("ldmatrix.sync.aligned.m8n8.x4.shared.b16 {%0,%1,%2,%3}, [%4];"
                 : "=r"(r[0]), "=r"(r[1]), "=r"(r[2]), "=r"(r[3]) : "r"(addr));
}
__device__ __forceinline__ void ldsm4t(uint32_t* r, uint32_t addr) {
    asm volatile("ldmatrix.sync.aligned.m8n8.x4.trans.shared.b16 {%0,%1,%2,%3}, [%4];"
                 : "=r"(r[0]), "=r"(r[1]), "=r"(r[2]), "=r"(r[3]) : "r"(addr));
}
__device__ __forceinline__ void cpa16(uint32_t dst, const void* src) {
    asm volatile("cp.async.ca.shared.global [%0], [%1], 16;"
                 :: "r"(dst), "l"(src) : "memory");
}
#define CPA_COMMIT asm volatile("cp.async.commit_group;" ::: "memory")
#define CPA_WAIT1  asm volatile("cp.async.wait_group 1;" ::: "memory")
#define CPA_WAIT0  asm volatile("cp.async.wait_group 0;" ::: "memory")

// ---------------- LayerNorm: one row per block, emits bf16 hi/lo ----------
__global__ void ln_kernel(const float* __restrict__ x,
                          const float* __restrict__ g,
                          const float* __restrict__ bta) {
    __shared__ float sh[8];
    __shared__ float bc[2];
    int row = blockIdx.x;
    int tid = threadIdx.x;
    int lane = tid & 31, wid = tid >> 5;

    const float4* xr = (const float4*)(x + (size_t)row * DD);
    float4 v = xr[tid];

    float s = v.x + v.y + v.z + v.w;
#pragma unroll
    for (int o = 16; o > 0; o >>= 1) s += __shfl_xor_sync(0xffffffffu, s, o);
    if (lane == 0) sh[wid] = s;
    __syncthreads();
    if (tid == 0) {
        float t = 0.f;
#pragma unroll
        for (int i = 0; i < 8; i++) t += sh[i];
        bc[0] = t;
    }
    __syncthreads();
    float mu = bc[0] * (1.f / DD);

    float dx = v.x - mu, dy = v.y - mu, dz = v.z - mu, dw = v.w - mu;

    float sq = dx*dx + dy*dy + dz*dz + dw*dw;
#pragma unroll
    for (int o = 16; o > 0; o >>= 1) sq += __shfl_xor_sync(0xffffffffu, sq, o);
    if (lane == 0) sh[wid] = sq;
    __syncthreads();
    if (tid == 0) {
        float t = 0.f;
#pragma unroll
        for (int i = 0; i < 8; i++) t += sh[i];
        bc[1] = t;
    }
    __syncthreads();
    float rs = rsqrtf(bc[1] * (1.f / DD) + 1e-5f);

    float4 gg = ((const float4*)g)[tid];
    float4 bb = ((const float4*)bta)[tid];
    float o0 = dx * rs * gg.x + bb.x;
    float o1 = dy * rs * gg.y + bb.y;
    float o2 = dz * rs * gg.z + bb.z;
    float o3 = dw * rs * gg.w + bb.w;

    bf16 h0, h1, h2, h3, l0, l1, l2, l3;
    split2(o0, h0, l0); split2(o1, h1, l1);
    split2(o2, h2, l2); split2(o3, h3, l3);
    size_t o = (size_t)row * DD + tid * 4;
    ushort4 hv = {us(h0), us(h1), us(h2), us(h3)};
    ushort4 lv = {us(l0), us(l1), us(l2), us(l3)};
    *(ushort4*)&g_xnh[o] = hv;
    *(ushort4*)&g_xnl[o] = lv;
}

// ---------------- weight transpose + split (once per launch) ---------------
__global__ void wq_cvt(const float* __restrict__ qkvw) {
    __shared__ float t[32][33];
    int l = blockIdx.z;
    int k0 = blockIdx.x * 32, n0 = blockIdx.y * 32;
    int chunk = n0 >> 7, head = chunk / 3, part = chunk % 3;
    int wbase = head * 512 + part * 128 + (n0 & 127);
    const float* W = qkvw + (size_t)l * DD * QKVW;
#pragma unroll
    for (int s = 0; s < 4; s++)
        t[threadIdx.y + 8*s][threadIdx.x] =
            W[(size_t)(k0 + threadIdx.y + 8*s) * QKVW + wbase + threadIdx.x];
    __syncthreads();
#pragma unroll
    for (int s = 0; s < 4; s++) {
        int n = n0 + threadIdx.y + 8*s;
        float v = t[threadIdx.x][threadIdx.y + 8*s];
        bf16 h, lo; split2(v, h, lo);
        size_t o = ((size_t)l * 3072 + n) * DD + k0 + threadIdx.x;
        g_wqh[o] = h; g_wql[o] = lo;
    }
}
__global__ void w2_cvt(const float* __restrict__ outw) {
    __shared__ float t[32][33];
    int l = blockIdx.z;
    int k0 = blockIdx.x * 32, n0 = blockIdx.y * 32;
    const float* W = outw + (size_t)l * DD * DD;
#pragma unroll
    for (int s = 0; s < 4; s++)
        t[threadIdx.y + 8*s][threadIdx.x] =
            W[(size_t)(k0 + threadIdx.y + 8*s) * DD + n0 + threadIdx.x];
    __syncthreads();
#pragma unroll
    for (int s = 0; s < 4; s++) {
        int n = n0 + threadIdx.y + 8*s;
        float v = t[threadIdx.x][threadIdx.y + 8*s];
        bf16 h, lo; split2(v, h, lo);
        size_t o = ((size_t)l * DD + n) * DD + k0 + threadIdx.x;
        g_w2h[o] = h; g_w2l[o] = lo;
    }
}

// ---------------- HMMA GEMM: 128x128 tile, BK=32, compile-time modes ------
// MODE 0: q/k hi-only (1 MMA, half smem)       grid (16, 64)
// MODE 1: v split-bf16 (3 MMA)                 grid (8, 64)
// MODE 2: X += attn @ Wout + bias (3 MMA)      grid (8, 64)
#define RSTR 80
#define HM_SMEM 81920

template<int MODE>
__global__ __launch_bounds__(256) void hmma_gemm(int layer,
                                                 const float* __restrict__ bias,
                                                 float* __restrict__ X) {
    constexpr bool LO = (MODE != 0);
    constexpr uint32_t OF_AH = 0;
    constexpr uint32_t OF_BH = 10240;
    constexpr uint32_t OF_AL = 20480;     // unused when !LO
    constexpr uint32_t OF_BL = 30720;
    constexpr uint32_t STG = LO ? 40960 : 20480;

    extern __shared__ char smem[];
    uint32_t sb = smem_u32(smem);
    int tid = threadIdx.x;
    int w = tid >> 5, lane = tid & 31;
    int row0 = blockIdx.y * 128;
    int bx = blockIdx.x;

    int head, part, bblk;
    if constexpr (MODE == 0) { head = bx >> 1; part = bx & 1; bblk = head * 3 + part; }
    else if constexpr (MODE == 1) { head = bx; part = 2; bblk = head * 3 + 2; }
    else { head = 0; part = 0; bblk = bx; }

    const bf16* Ah = ((MODE == 2) ? g_ath : g_xnh) + (size_t)row0 * DD;
    const bf16* Al = ((MODE == 2) ? g_atl : g_xnl) + (size_t)row0 * DD;
    const bf16* Bh = ((MODE == 2) ? (g_w2h + (size_t)layer * DD * DD)
                                  : (g_wqh + (size_t)layer * 3072 * DD))
                     + (size_t)bblk * 128 * DD;
    const bf16* Bl = ((MODE == 2) ? (g_w2l + (size_t)layer * DD * DD)
                                  : (g_wql + (size_t)layer * 3072 * DD))
                     + (size_t)bblk * 128 * DD;

    float c[4][4][4];
#pragma unroll
    for (int i = 0; i < 4; i++)
#pragma unroll
        for (int j = 0; j < 4; j++)
#pragma unroll
            for (int q = 0; q < 4; q++) c[i][j][q] = 0.f;

    int wm = w & 1, wn = w >> 1;
    int grp = lane >> 3, r8 = lane & 7;
    int arow = wm * 64 + (grp & 1) * 8 + r8;
    int akb0 = (grp >> 1) * 16;
    int brow = wn * 32 + (grp >> 1) * 8 + r8;
    int bkb0 = (grp & 1) * 16;

    auto prefetch = [&](int s) {
        uint32_t s0 = sb + (s & 1) * STG;
        int k0 = s * 32;
#pragma unroll
        for (int ch = tid; ch < 512; ch += 256) {
            int row = ch >> 2, cw = ch & 3;
            uint32_t so = row * RSTR + cw * 16;
            size_t go = (size_t)row * DD + k0 + cw * 8;
            cpa16(s0 + OF_AH + so, (const char*)(Ah + go));
            cpa16(s0 + OF_BH + so, (const char*)(Bh + go));
            if constexpr (LO) {
                cpa16(s0 + OF_AL + so, (const char*)(Al + go));
                cpa16(s0 + OF_BL + so, (const char*)(Bl + go));
            }
        }
        CPA_COMMIT;
    };
    prefetch(0);

    for (int s = 0; s < 32; s++) {
        if (s + 1 < 32) prefetch(s + 1);
        else CPA_COMMIT;
        CPA_WAIT1;
        __syncthreads();
        uint32_t base = sb + (s & 1) * STG;
#pragma unroll
        for (int k16 = 0; k16 < 2; k16++) {
            uint32_t ah[4][4], al[4][4], bh[2][4], bl[2][4];
            int akb = k16 * 32 + akb0;
            int bkb = k16 * 32 + bkb0;
#pragma unroll
            for (int i = 0; i < 4; i++) {
                uint32_t ao = (uint32_t)(arow + i * 16) * RSTR + akb;
                ldsm4(ah[i], base + OF_AH + ao);
                if constexpr (LO) ldsm4(al[i], base + OF_AL + ao);
            }
#pragma unroll
            for (int j = 0; j < 2; j++) {
                uint32_t bo = (uint32_t)(brow + j * 16) * RSTR + bkb;
                ldsm4(bh[j], base + OF_BH + bo);
                if constexpr (LO) ldsm4(bl[j], base + OF_BL + bo);
            }
#pragma unroll
            for (int i = 0; i < 4; i++)
#pragma unroll
                for (int jn = 0; jn < 4; jn++) {
                    const uint32_t* bph = &bh[jn >> 1][(jn & 1) * 2];
                    mma_bf16(c[i][jn], ah[i], bph);
                    if constexpr (LO) {
                        const uint32_t* bpl = &bl[jn >> 1][(jn & 1) * 2];
                        mma_bf16(c[i][jn], ah[i], bpl);
                        mma_bf16(c[i][jn], al[i], bph);
                    }
                }
        }
        __syncthreads();
    }
    CPA_WAIT0;

    int quad = lane >> 2, tq = lane & 3;
    if constexpr (MODE == 0) {
        int wcol0 = head * 512 + part * 128;
        bf16* dh = (part == 0) ? g_qh : g_kh;
        float scale = (part == 0) ? QSCALE : 1.f;
#pragma unroll
        for (int i = 0; i < 4; i++)
#pragma unroll
            for (int half = 0; half < 2; half++) {
                int r = row0 + wm * 64 + i * 16 + quad + half * 8;
                int b = r >> 11, n = r & (NN - 1);
                size_t ro = ((size_t)(b * HH + head) * NN + n) * 128;
#pragma unroll
                for (int jn = 0; jn < 4; jn++) {
                    int col = wn * 32 + jn * 8 + tq * 2;
                    float x0 = (c[i][jn][half*2+0] + bias[wcol0 + col]) * scale;
                    float x1 = (c[i][jn][half*2+1] + bias[wcol0 + col + 1]) * scale;
                    ushort2 hv = {us(__float2bfloat16(x0)),
                                  us(__float2bfloat16(x1))};
                    *(ushort2*)&dh[ro + col] = hv;
                }
            }
    } else if constexpr (MODE == 1) {
        int wcol0 = head * 512 + 2 * 128;
#pragma unroll
        for (int i = 0; i < 4; i++)
#pragma unroll
            for (int half = 0; half < 2; half++) {
                int r = row0 + wm * 64 + i * 16 + quad + half * 8;
                int b = r >> 11, n = r & (NN - 1);
                size_t ro = ((size_t)(b * HH + head) * NN + n) * 128;
#pragma unroll
                for (int jn = 0; jn < 4; jn++) {
                    int col = wn * 32 + jn * 8 + tq * 2;
                    float x0 = c[i][jn][half*2+0] + bias[wcol0 + col];
                    float x1 = c[i][jn][half*2+1] + bias[wcol0 + col + 1];
                    bf16 h0, l0, h1, l1;
                    split2(x0, h0, l0); split2(x1, h1, l1);
                    ushort2 hv = {us(h0), us(h1)};
                    ushort2 lv = {us(l0), us(l1)};
                    *(ushort2*)&g_vh[ro + col] = hv;
                    *(ushort2*)&g_vl[ro + col] = lv;
                }
            }
    } else {
        int col0 = bx * 128;
#pragma unroll
        for (int i = 0; i < 4; i++)
#pragma unroll
            for (int half = 0; half < 2; half++) {
                size_t r = row0 + wm * 64 + i * 16 + quad + half * 8;
#pragma unroll
                for (int jn = 0; jn < 4; jn++) {
                    int col = col0 + wn * 32 + jn * 8 + tq * 2;
                    float2 x = *(float2*)&X[r * DD + col];
                    x.x += c[i][jn][half*2+0] + bias[col];
                    x.y += c[i][jn][half*2+1] + bias[col + 1];
                    *(float2*)&X[r * DD + col] = x;
                }
            }
    }
}

// ---------------- suffix sums of V (chunked 2-pass) ------------------------
__global__ void sufA(const int* __restrict__ ids) {   // grid (NCK, 32), 128
    int ck = blockIdx.x, bh = blockIdx.y, b = bh >> 3;
    int d = threadIdx.x;
    size_t vbase = (size_t)bh * NN * 128 + d;
    int m0 = ck * CKR;
    float suf = 0.f, tot = 0.f, cnt = 0.f;
    for (int m = m0 + CKR - 1; m >= m0; m--) {
        float v = __bfloat162float(g_vh[vbase + (size_t)m * 128])
                + __bfloat162float(g_vl[vbase + (size_t)m * 128]);
        g_suf[((size_t)bh * NN + m) * 128 + d] = suf;
        if (d == 0) g_cnt[bh * NN + m] = cnt;
        tot += v;
        if (ids[b * NN + m] != 0) { suf += v; cnt += 1.f; }
    }
    g_ctv[(bh * NCK + ck) * 128 + d] = suf;
    g_ctu[(bh * NCK + ck) * 128 + d] = tot;
    if (d == 0) g_ckc[bh * NCK + ck] = cnt;
}
__global__ void sufB() {                              // grid (NCK, 32), 128
    int ck = blockIdx.x, bh = blockIdx.y;
    int d = threadIdx.x;
    float offs = 0.f, offc = 0.f;
    for (int cc = ck + 1; cc < NCK; cc++) {
        offs += g_ctv[(bh * NCK + cc) * 128 + d];
        offc += g_ckc[bh * NCK + cc];
    }
    if (ck == 0) {
        float t = 0.f;
        for (int cc = 0; cc < NCK; cc++) t += g_ctu[(bh * NCK + cc) * 128 + d];
        g_mv[bh * 128 + d] = t * INV_N;
    }
    int m0 = ck * CKR;
    if (ck < NCK - 1)
        for (int m = m0; m < m0 + CKR; m++) {
            g_suf[((size_t)bh * NN + m) * 128 + d] += offs;
            if (d == 0) g_cnt[bh * NN + m] += offc;
        }
}

// ---------------- attention: HMMA flash, 128-q CTA, 64-key tiles ----------
// p = exp(silu(s)/N) = 1 + d, d = l + l^2/2 (|l| < 3e-3 => Taylor exact).
// Mask part from SUF/CNT; kernel computes S = Q K^T and D.V, hi-only bf16.
#define AT_PITCH 272
#define AT_KH 0
#define AT_VH 17408
#define AT_STAGE 34816
#define AT_FLAGS (2*AT_STAGE)
#define ATTN_SMEM (AT_FLAGS + 512 + 512)

__global__ __launch_bounds__(256) void attn_kernel(const int* __restrict__ ids) {
    extern __shared__ char smem[];
    uint32_t sb = smem_u32(smem);
    int* vn  = (int*)(smem + AT_FLAGS);
    int* vmb = (int*)(smem + AT_FLAGS + 512);

    int tid = threadIdx.x;
    int w = tid >> 5, lane = tid & 31;
    int quad = lane >> 2, tq = lane & 3;
    int grp = lane >> 3, r8 = lane & 7;
    int n0 = blockIdx.x * 128;
    int h = blockIdx.y, b = blockIdx.z;
    int bh = b * HH + h;
    size_t base = (size_t)bh * NN * 128;

    // ---- stage Q (hi) into stage area, pull fragments to regs ----
    {
        const char* ph = (const char*)(g_qh + base + (size_t)n0 * 128);
        for (int ch = tid; ch < 2048; ch += 256) {
            int row = ch >> 4, c = ch & 15;
            cpa16(sb + row * AT_PITCH + c * 16, ph + row * 256 + c * 16);
        }
        CPA_COMMIT; CPA_WAIT0;
    }
    if (tid < 128) vn[tid] = (ids[b * NN + n0 + tid] != 0);
    __syncthreads();

    uint32_t qfh[8][4];
    {
        int arow = w * 16 + (grp & 1) * 8 + r8;
#pragma unroll
        for (int kt = 0; kt < 8; kt++) {
            uint32_t ao = (uint32_t)arow * AT_PITCH + kt * 32 + (grp >> 1) * 16;
            ldsm4(qfh[kt], sb + ao);
        }
    }
    __syncthreads();

    float o[16][4];
#pragma unroll
    for (int dt = 0; dt < 16; dt++)
#pragma unroll
        for (int q = 0; q < 4; q++) o[dt][q] = 0.f;
    float run_l[2] = {0.f, 0.f};

    const char* kh = (const char*)(g_kh + base);
    const char* vh = (const char*)(g_vh + base);

    int mt0 = n0 >> 6;
    auto prefetch = [&](int mt, int st) {
        int m0 = mt * 64;
        uint32_t s0 = sb + st * AT_STAGE;
        for (int ch = tid; ch < 1024; ch += 256) {
            int row = ch >> 4, c = ch & 15;
            uint32_t so = row * AT_PITCH + c * 16;
            size_t go = (size_t)(m0 + row) * 256 + c * 16;
            cpa16(s0 + AT_KH + so, kh + go);
            cpa16(s0 + AT_VH + so, vh + go);
        }
        if (tid < 64) vmb[st * 64 + tid] = (ids[b * NN + m0 + tid] != 0);
        CPA_COMMIT;
    };
    prefetch(mt0, 0);

    for (int mt = mt0; mt < NN / 64; mt++) {
        int st = (mt - mt0) & 1;
        if (mt + 1 < NN / 64) { prefetch(mt + 1, st ^ 1); CPA_WAIT1; }
        else                  { CPA_WAIT0; }
        __syncthreads();

        uint32_t stb = sb + st * AT_STAGE;
        int m0 = mt * 64;
        const int* vm = vmb + st * 64;

        // ---- S = Q K^T (hi-only, 64 MMAs) ----
        float s[8][4];
#pragma unroll
        for (int nt = 0; nt < 8; nt++)
#pragma unroll
            for (int q = 0; q < 4; q++) s[nt][q] = 0.f;
#pragma unroll
        for (int kt = 0; kt < 8; kt++) {
            uint32_t bh_[4][4];
#pragma unroll
            for (int ng = 0; ng < 4; ng++) {
                uint32_t ro = (uint32_t)(ng * 16 + (grp >> 1) * 8 + r8) * AT_PITCH
                            + kt * 32 + (grp & 1) * 16;
                ldsm4(bh_[ng], stb + AT_KH + ro);
            }
#pragma unroll
            for (int ng = 0; ng < 4; ng++)
#pragma unroll
                for (int hf = 0; hf < 2; hf++)
                    mma_bf16(s[ng * 2 + hf], qfh[kt], &bh_[ng][hf * 2]);
        }

        // ---- d = l + l^2/2, l = silu(s)/N, masked ----
#pragma unroll
        for (int hf = 0; hf < 2; hf++) {
            int rloc = w * 16 + quad + hf * 8;
            int n = n0 + rloc;
            int validn = vn[rloc];
            float psum = 0.f;
#pragma unroll
            for (int nt = 0; nt < 8; nt++)
#pragma unroll
                for (int c2 = 0; c2 < 2; c2++) {
                    int mloc = nt * 8 + tq * 2 + c2;
                    int m = m0 + mloc;
                    bool cc = (m > n) && validn && vm[mloc];
                    float sc = s[nt][hf * 2 + c2];
                    float l = __fdividef(sc, 1.f + __expf(-sc)) * INV_N;
                    float d = cc ? fmaf(0.5f * l, l, l) : 0.f;
                    s[nt][hf * 2 + c2] = d;
                    psum += d;
                }
            psum += __shfl_xor_sync(0xffffffffu, psum, 1);
            psum += __shfl_xor_sync(0xffffffffu, psum, 2);
            run_l[hf] += psum;
        }

        // ---- O += D V (D bf16 hi-only; V hi via ldmatrix.trans; 64 MMAs) --
#pragma unroll
        for (int kv = 0; kv < 4; kv++) {
            uint32_t dh[4];
#pragma unroll
            for (int half = 0; half < 2; half++) {
                int nt = kv * 2 + half;
                bf16 h0 = __float2bfloat16(s[nt][0]);
                bf16 h1 = __float2bfloat16(s[nt][1]);
                bf16 h2 = __float2bfloat16(s[nt][2]);
                bf16 h3 = __float2bfloat16(s[nt][3]);
                dh[half * 2 + 0] = pkbf(h0, h1);
                dh[half * 2 + 1] = pkbf(h2, h3);
            }
#pragma unroll
            for (int dg = 0; dg < 8; dg++) {
                uint32_t vfh[4];
                uint32_t ro = (uint32_t)(kv * 16 + (grp & 1) * 8 + r8) * AT_PITCH
                            + dg * 32 + (grp >> 1) * 16;
                ldsm4t(vfh, stb + AT_VH + ro);
#pragma unroll
                for (int hf = 0; hf < 2; hf++)
                    mma_bf16(o[dg * 2 + hf], dh, &vfh[hf * 2]);
            }
        }
        __syncthreads();
    }

    // ---- epilogue: O = (SUF + O_dev) / (CNT + sum_d), fallback -> meanV ----
#pragma unroll
    for (int hf = 0; hf < 2; hf++) {
        int rloc = w * 16 + quad + hf * 8;
        int n = n0 + rloc;
        int validn = vn[rloc];
        float cnt = g_cnt[bh * NN + n];
        bool fb = (!validn) || (cnt < 0.5f);
        float inv = fb ? 0.f : 1.f / (cnt + run_l[hf]);
        const float* sufp = g_suf + ((size_t)bh * NN + n) * 128;
        const float* mvp = g_mv + bh * 128;
        size_t orow = (size_t)(b * NN + n) * DD + h * 128;
#pragma unroll
        for (int dt = 0; dt < 16; dt++) {
            int d = dt * 8 + tq * 2;
            float x0, x1;
            if (fb) { x0 = mvp[d]; x1 = mvp[d + 1]; }
            else {
                float2 sv = *(const float2*)&sufp[d];
                x0 = (sv.x + o[dt][hf * 2 + 0]) * inv;
                x1 = (sv.y + o[dt][hf * 2 + 1]) * inv;
            }
            bf16 h0, l0, h1, l1;
            split2(x0, h0, l0); split2(x1, h1, l1);
            ushort2 hv = {us(h0), us(h1)};
            ushort2 lv = {us(l0), us(l1)};
            *(ushort2*)&g_ath[orow + d] = hv;
            *(ushort2*)&g_atl[orow + d] = lv;
        }
    }
}

// ---------------- launch ----------------
extern "C" void kernel_launch(void* const* d_in, const int* in_sizes, int n_in,
                              void* d_out, int out_size) {
    const int*   ids  = (const int*)d_in[1];     // past_ids (B,N)
    const float* emb  = (const float*)d_in[2];   // past_embeddings (B,N,D)
    const float* qkvw = (const float*)d_in[3];   // (4,1024,4096)
    const float* qkvb = (const float*)d_in[4];   // (4,4096)
    const float* outw = (const float*)d_in[5];   // (4,1024,1024)
    const float* outb = (const float*)d_in[6];   // (4,1024)
    const float* lng  = (const float*)d_in[7];   // (4,1024)
    const float* lnb  = (const float*)d_in[8];   // (4,1024)
    float* X = (float*)d_out;

    cudaFuncSetAttribute(attn_kernel,
                         cudaFuncAttributeMaxDynamicSharedMemorySize, ATTN_SMEM);
    cudaFuncSetAttribute(hmma_gemm<0>,
                         cudaFuncAttributeMaxDynamicSharedMemorySize, HM_SMEM);
    cudaFuncSetAttribute(hmma_gemm<1>,
                         cudaFuncAttributeMaxDynamicSharedMemorySize, HM_SMEM);
    cudaFuncSetAttribute(hmma_gemm<2>,
                         cudaFuncAttributeMaxDynamicSharedMemorySize, HM_SMEM);

    cudaMemcpyAsync(X, emb, sizeof(float) * (size_t)MM * DD,
                    cudaMemcpyDeviceToDevice);

    wq_cvt<<<dim3(32, 96, NBLK), dim3(32, 8)>>>(qkvw);
    w2_cvt<<<dim3(32, 32, NBLK), dim3(32, 8)>>>(outw);

    for (int l = 0; l < NBLK; l++) {
        ln_kernel<<<MM, 256>>>(X, lng + l * DD, lnb + l * DD);
        hmma_gemm<0><<<dim3(16, 64), 256, HM_SMEM>>>(l, qkvb + (size_t)l * QKVW, X);
        hmma_gemm<1><<<dim3(8, 64), 256, HM_SMEM>>>(l, qkvb + (size_t)l * QKVW, X);
        sufA<<<dim3(NCK, BB * HH), 128>>>(ids);
        sufB<<<dim3(NCK, BB * HH), 128>>>();
        attn_kernel<<<dim3(NN / 128, HH, BB), 256, ATTN_SMEM>>>(ids);
        hmma_gemm<2><<<dim3(8, 64), 256, HM_SMEM>>>(l, outb + (size_t)l * DD, X);
    }
}

// round 15
// speedup vs baseline: 1.9050x; 1.0289x over previous
#include <cuda_runtime.h>
#include <cuda_bf16.h>
#include <math.h>
#include <stdint.h>

#define BB 4
#define NN 2048
#define DD 1024
#define HH 8
#define NBLK 4
#define MM (BB*NN)          // 8192 rows
#define QKVW 4096
#define QSCALE 0.08838834764831845f   // 1/sqrt(128)
#define INV_N (1.0f/2048.0f)
#define NCK 8
#define CKR (NN/NCK)        // 256

typedef __nv_bfloat16 bf16;

// ---------------- scratch (device globals; no allocation allowed) ----------
__device__ bf16  g_xnh[MM*DD];           // ln output hi
__device__ bf16  g_xnl[MM*DD];           // ln output lo
__device__ bf16  g_qh[BB*HH*NN*128];     // q (scaled) bf16   [b,h,n,d]
__device__ bf16  g_kh[BB*HH*NN*128];     // k bf16
__device__ bf16  g_vh[BB*HH*NN*128];     // v hi
__device__ bf16  g_vl[BB*HH*NN*128];     // v lo
__device__ bf16  g_ath[MM*DD];           // attn output hi
__device__ bf16  g_atl[MM*DD];           // attn output lo
__device__ float g_mv [BB*HH*128];       // fallback: mean over ALL keys of v
__device__ float g_suf[(size_t)BB*HH*NN*128];  // 32 MB suffix sums
__device__ float g_cnt[BB*HH*NN];
__device__ float g_ctv[BB*HH*NCK*128];   // valid-gated chunk totals
__device__ float g_ctu[BB*HH*NCK*128];   // ungated chunk totals
__device__ float g_ckc[BB*HH*NCK];
__device__ bf16  g_wqh[(size_t)NBLK*3072*DD];  // qkv W^T hi  [l][n(3072)][k]
__device__ bf16  g_wql[(size_t)NBLK*3072*DD];
__device__ bf16  g_w2h[(size_t)NBLK*DD*DD];    // out W^T hi
__device__ bf16  g_w2l[(size_t)NBLK*DD*DD];

// ---------------- small helpers ----------------
__device__ __forceinline__ void split2(float x, bf16 &h, bf16 &l) {
    h = __float2bfloat16(x);
    l = __float2bfloat16(x - __bfloat162float(h));
}
__device__ __forceinline__ unsigned short us(bf16 h) { return __bfloat16_as_ushort(h); }
__device__ __forceinline__ uint32_t pkbf(bf16 lo, bf16 hi) {
    return ((uint32_t)us(hi) << 16) | us(lo);
}

// ---------------- HMMA path: mma.sync + ldmatrix + cp.async ---------------
__device__ __forceinline__ uint32_t smem_u32(const void* p) {
    uint32_t a;
    asm("{ .reg .u64 t; cvta.to.shared.u64 t, %1; cvt.u32.u64 %0, t; }"
        : "=r"(a) : "l"(p));
    return a;
}
__device__ __forceinline__ void mma_bf16(float* c, const uint32_t* a, const uint32_t* b) {
    asm volatile(
        "mma.sync.aligned.m16n8k16.row.col.f32.bf16.bf16.f32 "
        "{%0,%1,%2,%3}, {%4,%5,%6,%7}, {%8,%9}, {%0,%1,%2,%3};"
        : "+f"(c[0]), "+f"(c[1]), "+f"(c[2]), "+f"(c[3])
        : "r"(a[0]), "r"(a[1]), "r"(a[2]), "r"(a[3]), "r"(b[0]), "r"(b[1]));
}
__device__ __forceinline__ void ldsm4(uint32_t* r, uint32_t addr) {
    asm volatile("ldmatrix.sync.aligned.m8n8.x4.shared.b16 {%0,%1,%2,%3}, [%4];"
                 : "=r"(r[0]), "=r"(r[1]), "=r"(r[2]), "=r"(r[3]) : "r"(addr));
}
__device__ __forceinline__ void ldsm4t(uint32_t* r, uint32_t addr) {
    asm volatile("ldmatrix.sync.aligned.m8n8.x4.trans.shared.b16 {%0,%1,%2,%3}, [%4];"
                 : "=r"(r[0]), "=r"(r[1]), "=r"(r[2]), "=r"(r[3]) : "r"(addr));
}
__device__ __forceinline__ void cpa16(uint32_t dst, const void* src) {
    asm volatile("cp.async.ca.shared.global [%0], [%1], 16;"
                 :: "r"(dst), "l"(src) : "memory");
}
#define CPA_COMMIT asm volatile("cp.async.commit_group;" ::: "memory")
#define CPA_WAIT1  asm volatile("cp.async.wait_group 1;" ::: "memory")
#define CPA_WAIT0  asm volatile("cp.async.wait_group 0;" ::: "memory")

// ---------------- LayerNorm: one row per block, emits bf16 hi/lo ----------
__global__ void ln_kernel(const float* __restrict__ x,
                          const float* __restrict__ g,
                          const float* __restrict__ bta) {
    __shared__ float sh[8];
    __shared__ float bc[2];
    int row = blockIdx.x;
    int tid = threadIdx.x;
    int lane = tid & 31, wid = tid >> 5;

    const float4* xr = (const float4*)(x + (size_t)row * DD);
    float4 v = xr[tid];

    float s = v.x + v.y + v.z + v.w;
#pragma unroll
    for (int o = 16; o > 0; o >>= 1) s += __shfl_xor_sync(0xffffffffu, s, o);
    if (lane == 0) sh[wid] = s;
    __syncthreads();
    if (tid == 0) {
        float t = 0.f;
#pragma unroll
        for (int i = 0; i < 8; i++) t += sh[i];
        bc[0] = t;
    }
    __syncthreads();
    float mu = bc[0] * (1.f / DD);

    float dx = v.x - mu, dy = v.y - mu, dz = v.z - mu, dw = v.w - mu;

    float sq = dx*dx + dy*dy + dz*dz + dw*dw;
#pragma unroll
    for (int o = 16; o > 0; o >>= 1) sq += __shfl_xor_sync(0xffffffffu, sq, o);
    if (lane == 0) sh[wid] = sq;
    __syncthreads();
    if (tid == 0) {
        float t = 0.f;
#pragma unroll
        for (int i = 0; i < 8; i++) t += sh[i];
        bc[1] = t;
    }
    __syncthreads();
    float rs = rsqrtf(bc[1] * (1.f / DD) + 1e-5f);

    float4 gg = ((const float4*)g)[tid];
    float4 bb = ((const float4*)bta)[tid];
    float o0 = dx * rs * gg.x + bb.x;
    float o1 = dy * rs * gg.y + bb.y;
    float o2 = dz * rs * gg.z + bb.z;
    float o3 = dw * rs * gg.w + bb.w;

    bf16 h0, h1, h2, h3, l0, l1, l2, l3;
    split2(o0, h0, l0); split2(o1, h1, l1);
    split2(o2, h2, l2); split2(o3, h3, l3);
    size_t o = (size_t)row * DD + tid * 4;
    ushort4 hv = {us(h0), us(h1), us(h2), us(h3)};
    ushort4 lv = {us(l0), us(l1), us(l2), us(l3)};
    *(ushort4*)&g_xnh[o] = hv;
    *(ushort4*)&g_xnl[o] = lv;
}

// ---------------- weight transpose + split (once per launch) ---------------
__global__ void wq_cvt(const float* __restrict__ qkvw) {
    __shared__ float t[32][33];
    int l = blockIdx.z;
    int k0 = blockIdx.x * 32, n0 = blockIdx.y * 32;
    int chunk = n0 >> 7, head = chunk / 3, part = chunk % 3;
    int wbase = head * 512 + part * 128 + (n0 & 127);
    const float* W = qkvw + (size_t)l * DD * QKVW;
#pragma unroll
    for (int s = 0; s < 4; s++)
        t[threadIdx.y + 8*s][threadIdx.x] =
            W[(size_t)(k0 + threadIdx.y + 8*s) * QKVW + wbase + threadIdx.x];
    __syncthreads();
#pragma unroll
    for (int s = 0; s < 4; s++) {
        int n = n0 + threadIdx.y + 8*s;
        float v = t[threadIdx.x][threadIdx.y + 8*s];
        bf16 h, lo; split2(v, h, lo);
        size_t o = ((size_t)l * 3072 + n) * DD + k0 + threadIdx.x;
        g_wqh[o] = h; g_wql[o] = lo;
    }
}
__global__ void w2_cvt(const float* __restrict__ outw) {
    __shared__ float t[32][33];
    int l = blockIdx.z;
    int k0 = blockIdx.x * 32, n0 = blockIdx.y * 32;
    const float* W = outw + (size_t)l * DD * DD;
#pragma unroll
    for (int s = 0; s < 4; s++)
        t[threadIdx.y + 8*s][threadIdx.x] =
            W[(size_t)(k0 + threadIdx.y + 8*s) * DD + n0 + threadIdx.x];
    __syncthreads();
#pragma unroll
    for (int s = 0; s < 4; s++) {
        int n = n0 + threadIdx.y + 8*s;
        float v = t[threadIdx.x][threadIdx.y + 8*s];
        bf16 h, lo; split2(v, h, lo);
        size_t o = ((size_t)l * DD + n) * DD + k0 + threadIdx.x;
        g_w2h[o] = h; g_w2l[o] = lo;
    }
}

// ---------------- HMMA GEMM: 128x128 tile, compile-time modes -------------
// MODE 0: q/k hi-only (1 MMA), BK=64 stages          grid (16, 64)
// MODE 1: v split-bf16 (3 MMA), BK=32                grid (8, 64)
// MODE 2: X += attn @ Wout + bias (3 MMA), BK=32     grid (8, 64)
#define HM_SMEM0 73728
#define HM_SMEM12 81920

template<int MODE>
__global__ __launch_bounds__(256) void hmma_gemm(int layer,
                                                 const float* __restrict__ bias,
                                                 float* __restrict__ X) {
    constexpr bool LO = (MODE != 0);
    constexpr int BK = (MODE == 0) ? 64 : 32;
    constexpr uint32_t RS = (MODE == 0) ? 144 : 80;   // row pitch bytes (pad 16)
    constexpr uint32_t ASZ = 128 * RS;
    constexpr uint32_t OF_AH = 0;
    constexpr uint32_t OF_BH = ASZ;
    constexpr uint32_t OF_AL = 2 * ASZ;               // only when LO
    constexpr uint32_t OF_BL = 3 * ASZ;
    constexpr uint32_t STG = LO ? 4 * ASZ : 2 * ASZ;
    constexpr int NST = DD / BK;
    constexpr int NK16 = BK / 16;                     // k16 windows per stage
    constexpr int CPR = BK / 8;                       // 16B chunks per row
    constexpr int TOT = 128 * CPR;

    extern __shared__ char smem[];
    uint32_t sb = smem_u32(smem);
    int tid = threadIdx.x;
    int w = tid >> 5, lane = tid & 31;
    int row0 = blockIdx.y * 128;
    int bx = blockIdx.x;

    int head, part, bblk;
    if constexpr (MODE == 0) { head = bx >> 1; part = bx & 1; bblk = head * 3 + part; }
    else if constexpr (MODE == 1) { head = bx; part = 2; bblk = head * 3 + 2; }
    else { head = 0; part = 0; bblk = bx; }

    const bf16* Ah = ((MODE == 2) ? g_ath : g_xnh) + (size_t)row0 * DD;
    const bf16* Al = ((MODE == 2) ? g_atl : g_xnl) + (size_t)row0 * DD;
    const bf16* Bh = ((MODE == 2) ? (g_w2h + (size_t)layer * DD * DD)
                                  : (g_wqh + (size_t)layer * 3072 * DD))
                     + (size_t)bblk * 128 * DD;
    const bf16* Bl = ((MODE == 2) ? (g_w2l + (size_t)layer * DD * DD)
                                  : (g_wql + (size_t)layer * 3072 * DD))
                     + (size_t)bblk * 128 * DD;

    float c[4][4][4];
#pragma unroll
    for (int i = 0; i < 4; i++)
#pragma unroll
        for (int j = 0; j < 4; j++)
#pragma unroll
            for (int q = 0; q < 4; q++) c[i][j][q] = 0.f;

    int wm = w & 1, wn = w >> 1;
    int grp = lane >> 3, r8 = lane & 7;
    int arow = wm * 64 + (grp & 1) * 8 + r8;
    int akb0 = (grp >> 1) * 16;
    int brow = wn * 32 + (grp >> 1) * 8 + r8;
    int bkb0 = (grp & 1) * 16;

    auto prefetch = [&](int s) {
        uint32_t s0 = sb + (s & 1) * STG;
        int k0 = s * BK;
#pragma unroll
        for (int ch = tid; ch < TOT; ch += 256) {
            int row = ch / CPR, cw = ch % CPR;
            uint32_t so = row * RS + cw * 16;
            size_t go = (size_t)row * DD + k0 + cw * 8;
            cpa16(s0 + OF_AH + so, (const char*)(Ah + go));
            cpa16(s0 + OF_BH + so, (const char*)(Bh + go));
            if constexpr (LO) {
                cpa16(s0 + OF_AL + so, (const char*)(Al + go));
                cpa16(s0 + OF_BL + so, (const char*)(Bl + go));
            }
        }
        CPA_COMMIT;
    };
    prefetch(0);

    for (int s = 0; s < NST; s++) {
        if (s + 1 < NST) prefetch(s + 1);
        else CPA_COMMIT;
        CPA_WAIT1;
        __syncthreads();
        uint32_t base = sb + (s & 1) * STG;
#pragma unroll
        for (int k16 = 0; k16 < NK16; k16++) {
            uint32_t ah[4][4], al[4][4], bh[2][4], bl[2][4];
            int akb = k16 * 32 + akb0;
            int bkb = k16 * 32 + bkb0;
#pragma unroll
            for (int i = 0; i < 4; i++) {
                uint32_t ao = (uint32_t)(arow + i * 16) * RS + akb;
                ldsm4(ah[i], base + OF_AH + ao);
                if constexpr (LO) ldsm4(al[i], base + OF_AL + ao);
            }
#pragma unroll
            for (int j = 0; j < 2; j++) {
                uint32_t bo = (uint32_t)(brow + j * 16) * RS + bkb;
                ldsm4(bh[j], base + OF_BH + bo);
                if constexpr (LO) ldsm4(bl[j], base + OF_BL + bo);
            }
#pragma unroll
            for (int i = 0; i < 4; i++)
#pragma unroll
                for (int jn = 0; jn < 4; jn++) {
                    const uint32_t* bph = &bh[jn >> 1][(jn & 1) * 2];
                    mma_bf16(c[i][jn], ah[i], bph);
                    if constexpr (LO) {
                        const uint32_t* bpl = &bl[jn >> 1][(jn & 1) * 2];
                        mma_bf16(c[i][jn], ah[i], bpl);
                        mma_bf16(c[i][jn], al[i], bph);
                    }
                }
        }
        __syncthreads();
    }
    CPA_WAIT0;

    int quad = lane >> 2, tq = lane & 3;
    if constexpr (MODE == 0) {
        int wcol0 = head * 512 + part * 128;
        bf16* dh = (part == 0) ? g_qh : g_kh;
        float scale = (part == 0) ? QSCALE : 1.f;
#pragma unroll
        for (int i = 0; i < 4; i++)
#pragma unroll
            for (int half = 0; half < 2; half++) {
                int r = row0 + wm * 64 + i * 16 + quad + half * 8;
                int b = r >> 11, n = r & (NN - 1);
                size_t ro = ((size_t)(b * HH + head) * NN + n) * 128;
#pragma unroll
                for (int jn = 0; jn < 4; jn++) {
                    int col = wn * 32 + jn * 8 + tq * 2;
                    float x0 = (c[i][jn][half*2+0] + bias[wcol0 + col]) * scale;
                    float x1 = (c[i][jn][half*2+1] + bias[wcol0 + col + 1]) * scale;
                    ushort2 hv = {us(__float2bfloat16(x0)),
                                  us(__float2bfloat16(x1))};
                    *(ushort2*)&dh[ro + col] = hv;
                }
            }
    } else if constexpr (MODE == 1) {
        int wcol0 = head * 512 + 2 * 128;
#pragma unroll
        for (int i = 0; i < 4; i++)
#pragma unroll
            for (int half = 0; half < 2; half++) {
                int r = row0 + wm * 64 + i * 16 + quad + half * 8;
                int b = r >> 11, n = r & (NN - 1);
                size_t ro = ((size_t)(b * HH + head) * NN + n) * 128;
#pragma unroll
                for (int jn = 0; jn < 4; jn++) {
                    int col = wn * 32 + jn * 8 + tq * 2;
                    float x0 = c[i][jn][half*2+0] + bias[wcol0 + col];
                    float x1 = c[i][jn][half*2+1] + bias[wcol0 + col + 1];
                    bf16 h0, l0, h1, l1;
                    split2(x0, h0, l0); split2(x1, h1, l1);
                    ushort2 hv = {us(h0), us(h1)};
                    ushort2 lv = {us(l0), us(l1)};
                    *(ushort2*)&g_vh[ro + col] = hv;
                    *(ushort2*)&g_vl[ro + col] = lv;
                }
            }
    } else {
        int col0 = bx * 128;
#pragma unroll
        for (int i = 0; i < 4; i++)
#pragma unroll
            for (int half = 0; half < 2; half++) {
                size_t r = row0 + wm * 64 + i * 16 + quad + half * 8;
#pragma unroll
                for (int jn = 0; jn < 4; jn++) {
                    int col = col0 + wn * 32 + jn * 8 + tq * 2;
                    float2 x = *(float2*)&X[r * DD + col];
                    x.x += c[i][jn][half*2+0] + bias[col];
                    x.y += c[i][jn][half*2+1] + bias[col + 1];
                    *(float2*)&X[r * DD + col] = x;
                }
            }
    }
}

// ---------------- suffix sums of V (chunked 2-pass) ------------------------
__global__ void sufA(const int* __restrict__ ids) {   // grid (NCK, 32), 128
    int ck = blockIdx.x, bh = blockIdx.y, b = bh >> 3;
    int d = threadIdx.x;
    size_t vbase = (size_t)bh * NN * 128 + d;
    int m0 = ck * CKR;
    float suf = 0.f, tot = 0.f, cnt = 0.f;
    for (int m = m0 + CKR - 1; m >= m0; m--) {
        float v = __bfloat162float(g_vh[vbase + (size_t)m * 128])
                + __bfloat162float(g_vl[vbase + (size_t)m * 128]);
        g_suf[((size_t)bh * NN + m) * 128 + d] = suf;
        if (d == 0) g_cnt[bh * NN + m] = cnt;
        tot += v;
        if (ids[b * NN + m] != 0) { suf += v; cnt += 1.f; }
    }
    g_ctv[(bh * NCK + ck) * 128 + d] = suf;
    g_ctu[(bh * NCK + ck) * 128 + d] = tot;
    if (d == 0) g_ckc[bh * NCK + ck] = cnt;
}
__global__ void sufB() {                              // grid (NCK, 32), 128
    int ck = blockIdx.x, bh = blockIdx.y;
    int d = threadIdx.x;
    float offs = 0.f, offc = 0.f;
    for (int cc = ck + 1; cc < NCK; cc++) {
        offs += g_ctv[(bh * NCK + cc) * 128 + d];
        offc += g_ckc[bh * NCK + cc];
    }
    if (ck == 0) {
        float t = 0.f;
        for (int cc = 0; cc < NCK; cc++) t += g_ctu[(bh * NCK + cc) * 128 + d];
        g_mv[bh * 128 + d] = t * INV_N;
    }
    int m0 = ck * CKR;
    if (ck < NCK - 1)
        for (int m = m0; m < m0 + CKR; m++) {
            g_suf[((size_t)bh * NN + m) * 128 + d] += offs;
            if (d == 0) g_cnt[bh * NN + m] += offc;
        }
}

// ---------------- attention: HMMA flash, 128-q CTA, 64-key tiles ----------
// p = exp(silu(s)/N) = 1 + d, d = l + l^2/2 (|l| < 3e-3 => Taylor exact).
// Mask part from SUF/CNT; kernel computes S = Q K^T and D.V, hi-only bf16.
#define AT_PITCH 272
#define AT_KH 0
#define AT_VH 17408
#define AT_STAGE 34816
#define AT_FLAGS (2*AT_STAGE)
#define ATTN_SMEM (AT_FLAGS + 512 + 512)

__global__ __launch_bounds__(256) void attn_kernel(const int* __restrict__ ids) {
    extern __shared__ char smem[];
    uint32_t sb = smem_u32(smem);
    int* vn  = (int*)(smem + AT_FLAGS);
    int* vmb = (int*)(smem + AT_FLAGS + 512);

    int tid = threadIdx.x;
    int w = tid >> 5, lane = tid & 31;
    int quad = lane >> 2, tq = lane & 3;
    int grp = lane >> 3, r8 = lane & 7;
    int n0 = blockIdx.x * 128;
    int h = blockIdx.y, b = blockIdx.z;
    int bh = b * HH + h;
    size_t base = (size_t)bh * NN * 128;

    // ---- stage Q (hi) into stage area, pull fragments to regs ----
    {
        const char* ph = (const char*)(g_qh + base + (size_t)n0 * 128);
        for (int ch = tid; ch < 2048; ch += 256) {
            int row = ch >> 4, c = ch & 15;
            cpa16(sb + row * AT_PITCH + c * 16, ph + row * 256 + c * 16);
        }
        CPA_COMMIT; CPA_WAIT0;
    }
    if (tid < 128) vn[tid] = (ids[b * NN + n0 + tid] != 0);
    __syncthreads();

    uint32_t qfh[8][4];
    {
        int arow = w * 16 + (grp & 1) * 8 + r8;
#pragma unroll
        for (int kt = 0; kt < 8; kt++) {
            uint32_t ao = (uint32_t)arow * AT_PITCH + kt * 32 + (grp >> 1) * 16;
            ldsm4(qfh[kt], sb + ao);
        }
    }
    __syncthreads();

    float o[16][4];
#pragma unroll
    for (int dt = 0; dt < 16; dt++)
#pragma unroll
        for (int q = 0; q < 4; q++) o[dt][q] = 0.f;
    float run_l[2] = {0.f, 0.f};

    const char* kh = (const char*)(g_kh + base);
    const char* vh = (const char*)(g_vh + base);

    int mt0 = n0 >> 6;
    auto prefetch = [&](int mt, int st) {
        int m0 = mt * 64;
        uint32_t s0 = sb + st * AT_STAGE;
        for (int ch = tid; ch < 1024; ch += 256) {
            int row = ch >> 4, c = ch & 15;
            uint32_t so = row * AT_PITCH + c * 16;
            size_t go = (size_t)(m0 + row) * 256 + c * 16;
            cpa16(s0 + AT_KH + so, kh + go);
            cpa16(s0 + AT_VH + so, vh + go);
        }
        if (tid < 64) vmb[st * 64 + tid] = (ids[b * NN + m0 + tid] != 0);
        CPA_COMMIT;
    };
    prefetch(mt0, 0);

    for (int mt = mt0; mt < NN / 64; mt++) {
        int st = (mt - mt0) & 1;
        if (mt + 1 < NN / 64) { prefetch(mt + 1, st ^ 1); CPA_WAIT1; }
        else                  { CPA_WAIT0; }
        __syncthreads();

        uint32_t stb = sb + st * AT_STAGE;
        int m0 = mt * 64;
        const int* vm = vmb + st * 64;

        // ---- S = Q K^T (hi-only, 64 MMAs) ----
        float s[8][4];
#pragma unroll
        for (int nt = 0; nt < 8; nt++)
#pragma unroll
            for (int q = 0; q < 4; q++) s[nt][q] = 0.f;
#pragma unroll
        for (int kt = 0; kt < 8; kt++) {
            uint32_t bh_[4][4];
#pragma unroll
            for (int ng = 0; ng < 4; ng++) {
                uint32_t ro = (uint32_t)(ng * 16 + (grp >> 1) * 8 + r8) * AT_PITCH
                            + kt * 32 + (grp & 1) * 16;
                ldsm4(bh_[ng], stb + AT_KH + ro);
            }
#pragma unroll
            for (int ng = 0; ng < 4; ng++)
#pragma unroll
                for (int hf = 0; hf < 2; hf++)
                    mma_bf16(s[ng * 2 + hf], qfh[kt], &bh_[ng][hf * 2]);
        }

        // ---- d = l + l^2/2, l = silu(s)/N, masked ----
#pragma unroll
        for (int hf = 0; hf < 2; hf++) {
            int rloc = w * 16 + quad + hf * 8;
            int n = n0 + rloc;
            int validn = vn[rloc];
            float psum = 0.f;
#pragma unroll
            for (int nt = 0; nt < 8; nt++)
#pragma unroll
                for (int c2 = 0; c2 < 2; c2++) {
                    int mloc = nt * 8 + tq * 2 + c2;
                    int m = m0 + mloc;
                    bool cc = (m > n) && validn && vm[mloc];
                    float sc = s[nt][hf * 2 + c2];
                    float l = __fdividef(sc, 1.f + __expf(-sc)) * INV_N;
                    float d = cc ? fmaf(0.5f * l, l, l) : 0.f;
                    s[nt][hf * 2 + c2] = d;
                    psum += d;
                }
            psum += __shfl_xor_sync(0xffffffffu, psum, 1);
            psum += __shfl_xor_sync(0xffffffffu, psum, 2);
            run_l[hf] += psum;
        }

        // ---- O += D V (D bf16 hi-only; V hi via ldmatrix.trans; 64 MMAs) --
#pragma unroll
        for (int kv = 0; kv < 4; kv++) {
            uint32_t dh[4];
#pragma unroll
            for (int half = 0; half < 2; half++) {
                int nt = kv * 2 + half;
                bf16 h0 = __float2bfloat16(s[nt][0]);
                bf16 h1 = __float2bfloat16(s[nt][1]);
                bf16 h2 = __float2bfloat16(s[nt][2]);
                bf16 h3 = __float2bfloat16(s[nt][3]);
                dh[half * 2 + 0] = pkbf(h0, h1);
                dh[half * 2 + 1] = pkbf(h2, h3);
            }
#pragma unroll
            for (int dg = 0; dg < 8; dg++) {
                uint32_t vfh[4];
                uint32_t ro = (uint32_t)(kv * 16 + (grp & 1) * 8 + r8) * AT_PITCH
                            + dg * 32 + (grp >> 1) * 16;
                ldsm4t(vfh, stb + AT_VH + ro);
#pragma unroll
                for (int hf = 0; hf < 2; hf++)
                    mma_bf16(o[dg * 2 + hf], dh, &vfh[hf * 2]);
            }
        }
        __syncthreads();
    }

    // ---- epilogue: O = (SUF + O_dev) / (CNT + sum_d), fallback -> meanV ----
#pragma unroll
    for (int hf = 0; hf < 2; hf++) {
        int rloc = w * 16 + quad + hf * 8;
        int n = n0 + rloc;
        int validn = vn[rloc];
        float cnt = g_cnt[bh * NN + n];
        bool fb = (!validn) || (cnt < 0.5f);
        float inv = fb ? 0.f : 1.f / (cnt + run_l[hf]);
        const float* sufp = g_suf + ((size_t)bh * NN + n) * 128;
        const float* mvp = g_mv + bh * 128;
        size_t orow = (size_t)(b * NN + n) * DD + h * 128;
#pragma unroll
        for (int dt = 0; dt < 16; dt++) {
            int d = dt * 8 + tq * 2;
            float x0, x1;
            if (fb) { x0 = mvp[d]; x1 = mvp[d + 1]; }
            else {
                float2 sv = *(const float2*)&sufp[d];
                x0 = (sv.x + o[dt][hf * 2 + 0]) * inv;
                x1 = (sv.y + o[dt][hf * 2 + 1]) * inv;
            }
            bf16 h0, l0, h1, l1;
            split2(x0, h0, l0); split2(x1, h1, l1);
            ushort2 hv = {us(h0), us(h1)};
            ushort2 lv = {us(l0), us(l1)};
            *(ushort2*)&g_ath[orow + d] = hv;
            *(ushort2*)&g_atl[orow + d] = lv;
        }
    }
}

// ---------------- launch ----------------
extern "C" void kernel_launch(void* const* d_in, const int* in_sizes, int n_in,
                              void* d_out, int out_size) {
    const int*   ids  = (const int*)d_in[1];     // past_ids (B,N)
    const float* emb  = (const float*)d_in[2];   // past_embeddings (B,N,D)
    const float* qkvw = (const float*)d_in[3];   // (4,1024,4096)
    const float* qkvb = (const float*)d_in[4];   // (4,4096)
    const float* outw = (const float*)d_in[5];   // (4,1024,1024)
    const float* outb = (const float*)d_in[6];   // (4,1024)
    const float* lng  = (const float*)d_in[7];   // (4,1024)
    const float* lnb  = (const float*)d_in[8];   // (4,1024)
    float* X = (float*)d_out;

    cudaFuncSetAttribute(attn_kernel,
                         cudaFuncAttributeMaxDynamicSharedMemorySize, ATTN_SMEM);
    cudaFuncSetAttribute(hmma_gemm<0>,
                         cudaFuncAttributeMaxDynamicSharedMemorySize, HM_SMEM0);
    cudaFuncSetAttribute(hmma_gemm<1>,
                         cudaFuncAttributeMaxDynamicSharedMemorySize, HM_SMEM12);
    cudaFuncSetAttribute(hmma_gemm<2>,
                         cudaFuncAttributeMaxDynamicSharedMemorySize, HM_SMEM12);

    // side stream + events for per-layer overlap of independent chains.
    // Created per call (few calls total; not device memory). Event-edge fork
    // pattern is graph-capture-legal: waits enroll the side stream into the
    // capture, and it joins back before return.
    cudaStream_t side;
    cudaStreamCreateWithFlags(&side, cudaStreamNonBlocking);
    cudaEvent_t evF[NBLK], evJ[NBLK];
    for (int l = 0; l < NBLK; l++) {
        cudaEventCreateWithFlags(&evF[l], cudaEventDisableTiming);
        cudaEventCreateWithFlags(&evJ[l], cudaEventDisableTiming);
    }

    cudaMemcpyAsync(X, emb, sizeof(float) * (size_t)MM * DD,
                    cudaMemcpyDeviceToDevice);

    wq_cvt<<<dim3(32, 96, NBLK), dim3(32, 8)>>>(qkvw);
    w2_cvt<<<dim3(32, 32, NBLK), dim3(32, 8)>>>(outw);

    for (int l = 0; l < NBLK; l++) {
        ln_kernel<<<MM, 256>>>(X, lng + l * DD, lnb + l * DD);
        cudaEventRecord(evF[l], 0);
        cudaStreamWaitEvent(side, evF[l], 0);
        // main stream: q/k GEMM
        hmma_gemm<0><<<dim3(16, 64), 256, HM_SMEM0>>>(l, qkvb + (size_t)l * QKVW, X);
        // side stream: v GEMM -> suffix sums
        hmma_gemm<1><<<dim3(8, 64), 256, HM_SMEM12, side>>>(l, qkvb + (size_t)l * QKVW, X);
        sufA<<<dim3(NCK, BB * HH), 128, 0, side>>>(ids);
        sufB<<<dim3(NCK, BB * HH), 128, 0, side>>>();
        cudaEventRecord(evJ[l], side);
        cudaStreamWaitEvent(0, evJ[l], 0);
        attn_kernel<<<dim3(NN / 128, HH, BB), 256, ATTN_SMEM>>>(ids);
        hmma_gemm<2><<<dim3(8, 64), 256, HM_SMEM12>>>(l, outb + (size_t)l * DD, X);
    }
}

// round 16
// speedup vs baseline: 2.0969x; 1.1007x over previous
#include <cuda_runtime.h>
#include <cuda_bf16.h>
#include <math.h>
#include <stdint.h>

#define BB 4
#define NN 2048
#define DD 1024
#define HH 8
#define NBLK 4
#define MM (BB*NN)          // 8192 rows
#define QKVW 4096
#define QSCALE 0.08838834764831845f   // 1/sqrt(128)
#define INV_N (1.0f/2048.0f)
#define NCK 8
#define CKR (NN/NCK)        // 256

typedef __nv_bfloat16 bf16;

// ---------------- scratch (device globals; no allocation allowed) ----------
__device__ bf16  g_xnh[MM*DD];           // ln output hi
__device__ bf16  g_xnl[MM*DD];           // ln output lo
__device__ bf16  g_qh[BB*HH*NN*128];     // q (scaled) bf16   [b,h,n,d]
__device__ bf16  g_kh[BB*HH*NN*128];     // k bf16 (invalid keys zeroed)
__device__ bf16  g_vh[BB*HH*NN*128];     // v hi
__device__ bf16  g_vl[BB*HH*NN*128];     // v lo
__device__ bf16  g_ath[MM*DD];           // attn output hi
__device__ bf16  g_atl[MM*DD];           // attn output lo
__device__ float g_mv [BB*HH*128];       // fallback: mean over ALL keys of v
__device__ float g_suf[(size_t)BB*HH*NN*128];  // chunk-local suffix sums
__device__ float g_cnt[BB*HH*NN];              // chunk-local suffix counts
__device__ float g_ctv[BB*HH*NCK*128];   // valid-gated chunk totals
__device__ float g_ctu[BB*HH*NCK*128];   // ungated chunk totals
__device__ float g_ckc[BB*HH*NCK];
__device__ float g_ctp[BB*HH*NCK*128];   // suffix-prefix of ctv over chunks
__device__ float g_ckp[BB*HH*NCK];       // suffix-prefix of ckc
__device__ bf16  g_wqh[(size_t)NBLK*3072*DD];  // qkv W^T hi  [l][n(3072)][k]
__device__ bf16  g_wql[(size_t)NBLK*3072*DD];
__device__ bf16  g_w2h[(size_t)NBLK*DD*DD];    // out W^T hi
__device__ bf16  g_w2l[(size_t)NBLK*DD*DD];

// ---------------- small helpers ----------------
__device__ __forceinline__ void split2(float x, bf16 &h, bf16 &l) {
    h = __float2bfloat16(x);
    l = __float2bfloat16(x - __bfloat162float(h));
}
__device__ __forceinline__ unsigned short us(bf16 h) { return __bfloat16_as_ushort(h); }
__device__ __forceinline__ uint32_t pkbf(bf16 lo, bf16 hi) {
    return ((uint32_t)us(hi) << 16) | us(lo);
}

// ---------------- HMMA path: mma.sync + ldmatrix + cp.async ---------------
__device__ __forceinline__ uint32_t smem_u32(const void* p) {
    uint32_t a;
    asm("{ .reg .u64 t; cvta.to.shared.u64 t, %1; cvt.u32.u64 %0, t; }"
        : "=r"(a) : "l"(p));
    return a;
}
__device__ __forceinline__ void mma_bf16(float* c, const uint32_t* a, const uint32_t* b) {
    asm volatile(
        "mma.sync.aligned.m16n8k16.row.col.f32.bf16.bf16.f32 "
        "{%0,%1,%2,%3}, {%4,%5,%6,%7}, {%8,%9}, {%0,%1,%2,%3};"
        : "+f"(c[0]), "+f"(c[1]), "+f"(c[2]), "+f"(c[3])
        : "r"(a[0]), "r"(a[1]), "r"(a[2]), "r"(a[3]), "r"(b[0]), "r"(b[1]));
}
__device__ __forceinline__ void ldsm4(uint32_t* r, uint32_t addr) {
    asm volatile("ldmatrix.sync.aligned.m8n8.x4.shared.b16 {%0,%1,%2,%3}, [%4];"
                 : "=r"(r[0]), "=r"(r[1]), "=r"(r[2]), "=r"(r[3]) : "r"(addr));
}
__device__ __forceinline__ void ldsm4t(uint32_t* r, uint32_t addr) {
    asm volatile("ldmatrix.sync.aligned.m8n8.x4.trans.shared.b16 {%0,%1,%2,%3}, [%4];"
                 : "=r"(r[0]), "=r"(r[1]), "=r"(r[2]), "=r"(r[3]) : "r"(addr));
}
__device__ __forceinline__ void cpa16(uint32_t dst, const void* src) {
    asm volatile("cp.async.ca.shared.global [%0], [%1], 16;"
                 :: "r"(dst), "l"(src) : "memory");
}
#define CPA_COMMIT asm volatile("cp.async.commit_group;" ::: "memory")
#define CPA_WAIT1  asm volatile("cp.async.wait_group 1;" ::: "memory")
#define CPA_WAIT0  asm volatile("cp.async.wait_group 0;" ::: "memory")

// ---------------- LayerNorm: one row per block, emits bf16 hi/lo ----------
__global__ void ln_kernel(const float* __restrict__ x,
                          const float* __restrict__ g,
                          const float* __restrict__ bta) {
    __shared__ float sh[8];
    __shared__ float bc[2];
    int row = blockIdx.x;
    int tid = threadIdx.x;
    int lane = tid & 31, wid = tid >> 5;

    const float4* xr = (const float4*)(x + (size_t)row * DD);
    float4 v = xr[tid];

    float s = v.x + v.y + v.z + v.w;
#pragma unroll
    for (int o = 16; o > 0; o >>= 1) s += __shfl_xor_sync(0xffffffffu, s, o);
    if (lane == 0) sh[wid] = s;
    __syncthreads();
    if (tid == 0) {
        float t = 0.f;
#pragma unroll
        for (int i = 0; i < 8; i++) t += sh[i];
        bc[0] = t;
    }
    __syncthreads();
    float mu = bc[0] * (1.f / DD);

    float dx = v.x - mu, dy = v.y - mu, dz = v.z - mu, dw = v.w - mu;

    float sq = dx*dx + dy*dy + dz*dz + dw*dw;
#pragma unroll
    for (int o = 16; o > 0; o >>= 1) sq += __shfl_xor_sync(0xffffffffu, sq, o);
    if (lane == 0) sh[wid] = sq;
    __syncthreads();
    if (tid == 0) {
        float t = 0.f;
#pragma unroll
        for (int i = 0; i < 8; i++) t += sh[i];
        bc[1] = t;
    }
    __syncthreads();
    float rs = rsqrtf(bc[1] * (1.f / DD) + 1e-5f);

    float4 gg = ((const float4*)g)[tid];
    float4 bb = ((const float4*)bta)[tid];
    float o0 = dx * rs * gg.x + bb.x;
    float o1 = dy * rs * gg.y + bb.y;
    float o2 = dz * rs * gg.z + bb.z;
    float o3 = dw * rs * gg.w + bb.w;

    bf16 h0, h1, h2, h3, l0, l1, l2, l3;
    split2(o0, h0, l0); split2(o1, h1, l1);
    split2(o2, h2, l2); split2(o3, h3, l3);
    size_t o = (size_t)row * DD + tid * 4;
    ushort4 hv = {us(h0), us(h1), us(h2), us(h3)};
    ushort4 lv = {us(l0), us(l1), us(l2), us(l3)};
    *(ushort4*)&g_xnh[o] = hv;
    *(ushort4*)&g_xnl[o] = lv;
}

// ---------------- weight transpose + split (once per launch) ---------------
__global__ void wq_cvt(const float* __restrict__ qkvw) {
    __shared__ float t[32][33];
    int l = blockIdx.z;
    int k0 = blockIdx.x * 32, n0 = blockIdx.y * 32;
    int chunk = n0 >> 7, head = chunk / 3, part = chunk % 3;
    int wbase = head * 512 + part * 128 + (n0 & 127);
    const float* W = qkvw + (size_t)l * DD * QKVW;
#pragma unroll
    for (int s = 0; s < 4; s++)
        t[threadIdx.y + 8*s][threadIdx.x] =
            W[(size_t)(k0 + threadIdx.y + 8*s) * QKVW + wbase + threadIdx.x];
    __syncthreads();
#pragma unroll
    for (int s = 0; s < 4; s++) {
        int n = n0 + threadIdx.y + 8*s;
        float v = t[threadIdx.x][threadIdx.y + 8*s];
        bf16 h, lo; split2(v, h, lo);
        size_t o = ((size_t)l * 3072 + n) * DD + k0 + threadIdx.x;
        g_wqh[o] = h; g_wql[o] = lo;
    }
}
__global__ void w2_cvt(const float* __restrict__ outw) {
    __shared__ float t[32][33];
    int l = blockIdx.z;
    int k0 = blockIdx.x * 32, n0 = blockIdx.y * 32;
    const float* W = outw + (size_t)l * DD * DD;
#pragma unroll
    for (int s = 0; s < 4; s++)
        t[threadIdx.y + 8*s][threadIdx.x] =
            W[(size_t)(k0 + threadIdx.y + 8*s) * DD + n0 + threadIdx.x];
    __syncthreads();
#pragma unroll
    for (int s = 0; s < 4; s++) {
        int n = n0 + threadIdx.y + 8*s;
        float v = t[threadIdx.x][threadIdx.y + 8*s];
        bf16 h, lo; split2(v, h, lo);
        size_t o = ((size_t)l * DD + n) * DD + k0 + threadIdx.x;
        g_w2h[o] = h; g_w2l[o] = lo;
    }
}

// ---------------- HMMA GEMM: 128x128 tile, compile-time modes -------------
// MODE 0: q/k hi-only (1 MMA), BK=64; invalid keys stored as k=0
// MODE 1: v split-bf16 (3 MMA), BK=32
// MODE 2: X += attn @ Wout + bias (3 MMA), BK=32
#define HM_SMEM0 73728
#define HM_SMEM12 81920

template<int MODE>
__global__ __launch_bounds__(256) void hmma_gemm(int layer,
                                                 const float* __restrict__ bias,
                                                 float* __restrict__ X,
                                                 const int* __restrict__ ids) {
    constexpr bool LO = (MODE != 0);
    constexpr int BK = (MODE == 0) ? 64 : 32;
    constexpr uint32_t RS = (MODE == 0) ? 144 : 80;   // row pitch bytes (pad 16)
    constexpr uint32_t ASZ = 128 * RS;
    constexpr uint32_t OF_AH = 0;
    constexpr uint32_t OF_BH = ASZ;
    constexpr uint32_t OF_AL = 2 * ASZ;               // only when LO
    constexpr uint32_t OF_BL = 3 * ASZ;
    constexpr uint32_t STG = LO ? 4 * ASZ : 2 * ASZ;
    constexpr int NST = DD / BK;
    constexpr int NK16 = BK / 16;                     // k16 windows per stage
    constexpr int CPR = BK / 8;                       // 16B chunks per row
    constexpr int TOT = 128 * CPR;

    extern __shared__ char smem[];
    uint32_t sb = smem_u32(smem);
    int tid = threadIdx.x;
    int w = tid >> 5, lane = tid & 31;
    int row0 = blockIdx.y * 128;
    int bx = blockIdx.x;

    int head, part, bblk;
    if constexpr (MODE == 0) { head = bx >> 1; part = bx & 1; bblk = head * 3 + part; }
    else if constexpr (MODE == 1) { head = bx; part = 2; bblk = head * 3 + 2; }
    else { head = 0; part = 0; bblk = bx; }

    const bf16* Ah = ((MODE == 2) ? g_ath : g_xnh) + (size_t)row0 * DD;
    const bf16* Al = ((MODE == 2) ? g_atl : g_xnl) + (size_t)row0 * DD;
    const bf16* Bh = ((MODE == 2) ? (g_w2h + (size_t)layer * DD * DD)
                                  : (g_wqh + (size_t)layer * 3072 * DD))
                     + (size_t)bblk * 128 * DD;
    const bf16* Bl = ((MODE == 2) ? (g_w2l + (size_t)layer * DD * DD)
                                  : (g_wql + (size_t)layer * 3072 * DD))
                     + (size_t)bblk * 128 * DD;

    float c[4][4][4];
#pragma unroll
    for (int i = 0; i < 4; i++)
#pragma unroll
        for (int j = 0; j < 4; j++)
#pragma unroll
            for (int q = 0; q < 4; q++) c[i][j][q] = 0.f;

    int wm = w & 1, wn = w >> 1;
    int grp = lane >> 3, r8 = lane & 7;
    int arow = wm * 64 + (grp & 1) * 8 + r8;
    int akb0 = (grp >> 1) * 16;
    int brow = wn * 32 + (grp >> 1) * 8 + r8;
    int bkb0 = (grp & 1) * 16;

    auto prefetch = [&](int s) {
        uint32_t s0 = sb + (s & 1) * STG;
        int k0 = s * BK;
#pragma unroll
        for (int ch = tid; ch < TOT; ch += 256) {
            int row = ch / CPR, cw = ch % CPR;
            uint32_t so = row * RS + cw * 16;
            size_t go = (size_t)row * DD + k0 + cw * 8;
            cpa16(s0 + OF_AH + so, (const char*)(Ah + go));
            cpa16(s0 + OF_BH + so, (const char*)(Bh + go));
            if constexpr (LO) {
                cpa16(s0 + OF_AL + so, (const char*)(Al + go));
                cpa16(s0 + OF_BL + so, (const char*)(Bl + go));
            }
        }
        CPA_COMMIT;
    };
    prefetch(0);

    for (int s = 0; s < NST; s++) {
        if (s + 1 < NST) prefetch(s + 1);
        else CPA_COMMIT;
        CPA_WAIT1;
        __syncthreads();
        uint32_t base = sb + (s & 1) * STG;
#pragma unroll
        for (int k16 = 0; k16 < NK16; k16++) {
            uint32_t ah[4][4], al[4][4], bh[2][4], bl[2][4];
            int akb = k16 * 32 + akb0;
            int bkb = k16 * 32 + bkb0;
#pragma unroll
            for (int i = 0; i < 4; i++) {
                uint32_t ao = (uint32_t)(arow + i * 16) * RS + akb;
                ldsm4(ah[i], base + OF_AH + ao);
                if constexpr (LO) ldsm4(al[i], base + OF_AL + ao);
            }
#pragma unroll
            for (int j = 0; j < 2; j++) {
                uint32_t bo = (uint32_t)(brow + j * 16) * RS + bkb;
                ldsm4(bh[j], base + OF_BH + bo);
                if constexpr (LO) ldsm4(bl[j], base + OF_BL + bo);
            }
#pragma unroll
            for (int i = 0; i < 4; i++)
#pragma unroll
                for (int jn = 0; jn < 4; jn++) {
                    const uint32_t* bph = &bh[jn >> 1][(jn & 1) * 2];
                    mma_bf16(c[i][jn], ah[i], bph);
                    if constexpr (LO) {
                        const uint32_t* bpl = &bl[jn >> 1][(jn & 1) * 2];
                        mma_bf16(c[i][jn], ah[i], bpl);
                        mma_bf16(c[i][jn], al[i], bph);
                    }
                }
        }
        __syncthreads();
    }
    CPA_WAIT0;

    int quad = lane >> 2, tq = lane & 3;
    if constexpr (MODE == 0) {
        int wcol0 = head * 512 + part * 128;
        bf16* dh = (part == 0) ? g_qh : g_kh;
        float scale = (part == 0) ? QSCALE : 1.f;
#pragma unroll
        for (int i = 0; i < 4; i++)
#pragma unroll
            for (int half = 0; half < 2; half++) {
                int r = row0 + wm * 64 + i * 16 + quad + half * 8;
                int b = r >> 11, n = r & (NN - 1);
                size_t ro = ((size_t)(b * HH + head) * NN + n) * 128;
                // k rows of invalid keys are zeroed: s = q.k = 0 => d = 0
                float keep = (part == 1 && ids[b * NN + n] == 0) ? 0.f : 1.f;
#pragma unroll
                for (int jn = 0; jn < 4; jn++) {
                    int col = wn * 32 + jn * 8 + tq * 2;
                    float x0 = (c[i][jn][half*2+0] + bias[wcol0 + col]) * scale * keep;
                    float x1 = (c[i][jn][half*2+1] + bias[wcol0 + col + 1]) * scale * keep;
                    ushort2 hv = {us(__float2bfloat16(x0)),
                                  us(__float2bfloat16(x1))};
                    *(ushort2*)&dh[ro + col] = hv;
                }
            }
    } else if constexpr (MODE == 1) {
        int wcol0 = head * 512 + 2 * 128;
#pragma unroll
        for (int i = 0; i < 4; i++)
#pragma unroll
            for (int half = 0; half < 2; half++) {
                int r = row0 + wm * 64 + i * 16 + quad + half * 8;
                int b = r >> 11, n = r & (NN - 1);
                size_t ro = ((size_t)(b * HH + head) * NN + n) * 128;
#pragma unroll
                for (int jn = 0; jn < 4; jn++) {
                    int col = wn * 32 + jn * 8 + tq * 2;
                    float x0 = c[i][jn][half*2+0] + bias[wcol0 + col];
                    float x1 = c[i][jn][half*2+1] + bias[wcol0 + col + 1];
                    bf16 h0, l0, h1, l1;
                    split2(x0, h0, l0); split2(x1, h1, l1);
                    ushort2 hv = {us(h0), us(h1)};
                    ushort2 lv = {us(l0), us(l1)};
                    *(ushort2*)&g_vh[ro + col] = hv;
                    *(ushort2*)&g_vl[ro + col] = lv;
                }
            }
    } else {
        int col0 = bx * 128;
#pragma unroll
        for (int i = 0; i < 4; i++)
#pragma unroll
            for (int half = 0; half < 2; half++) {
                size_t r = row0 + wm * 64 + i * 16 + quad + half * 8;
#pragma unroll
                for (int jn = 0; jn < 4; jn++) {
                    int col = col0 + wn * 32 + jn * 8 + tq * 2;
                    float2 x = *(float2*)&X[r * DD + col];
                    x.x += c[i][jn][half*2+0] + bias[col];
                    x.y += c[i][jn][half*2+1] + bias[col + 1];
                    *(float2*)&X[r * DD + col] = x;
                }
            }
    }
}

// ---------------- suffix sums of V (chunk-local + tiny prefix) -------------
__global__ void sufA(const int* __restrict__ ids) {   // grid (NCK, 32), 128
    int ck = blockIdx.x, bh = blockIdx.y, b = bh >> 3;
    int d = threadIdx.x;
    size_t vbase = (size_t)bh * NN * 128 + d;
    int m0 = ck * CKR;
    float suf = 0.f, tot = 0.f, cnt = 0.f;
    for (int m = m0 + CKR - 1; m >= m0; m--) {
        float v = __bfloat162float(g_vh[vbase + (size_t)m * 128])
                + __bfloat162float(g_vl[vbase + (size_t)m * 128]);
        g_suf[((size_t)bh * NN + m) * 128 + d] = suf;
        if (d == 0) g_cnt[bh * NN + m] = cnt;
        tot += v;
        if (ids[b * NN + m] != 0) { suf += v; cnt += 1.f; }
    }
    g_ctv[(bh * NCK + ck) * 128 + d] = suf;
    g_ctu[(bh * NCK + ck) * 128 + d] = tot;
    if (d == 0) g_ckc[bh * NCK + ck] = cnt;
}
// tiny: per (bh,d) compute suffix-prefix tables + meanV (replaces 32MB rewrite)
__global__ void sufB() {                              // grid (32), 128
    int bh = blockIdx.x;
    int d = threadIdx.x;
    float t = 0.f;
#pragma unroll
    for (int cc = 0; cc < NCK; cc++) t += g_ctu[(bh * NCK + cc) * 128 + d];
    g_mv[bh * 128 + d] = t * INV_N;
    float acc = 0.f;
#pragma unroll
    for (int ck = NCK - 1; ck >= 0; ck--) {
        g_ctp[(bh * NCK + ck) * 128 + d] = acc;
        acc += g_ctv[(bh * NCK + ck) * 128 + d];
    }
    if (d == 0) {
        float ac = 0.f;
#pragma unroll
        for (int ck = NCK - 1; ck >= 0; ck--) {
            g_ckp[bh * NCK + ck] = ac;
            ac += g_ckc[bh * NCK + ck];
        }
    }
}

// ---------------- attention: HMMA flash, 128-q CTA, 64-key tiles ----------
// Invalid keys have k=0 => s=0 => d=0; invalid queries use the fallback path.
// So the mainloop mask is just (m > n). d = l + l^2/2, l = silu(s)/N.
#define AT_PITCH 272
#define AT_KH 0
#define AT_VH 17408
#define AT_STAGE 34816
#define ATTN_SMEM (2*AT_STAGE)

__global__ __launch_bounds__(256) void attn_kernel(const int* __restrict__ ids) {
    extern __shared__ char smem[];
    uint32_t sb = smem_u32(smem);

    int tid = threadIdx.x;
    int w = tid >> 5, lane = tid & 31;
    int quad = lane >> 2, tq = lane & 3;
    int grp = lane >> 3, r8 = lane & 7;
    int n0 = blockIdx.x * 128;
    int h = blockIdx.y, b = blockIdx.z;
    int bh = b * HH + h;
    size_t base = (size_t)bh * NN * 128;

    // ---- stage Q (hi) into stage area, pull fragments to regs ----
    {
        const char* ph = (const char*)(g_qh + base + (size_t)n0 * 128);
        for (int ch = tid; ch < 2048; ch += 256) {
            int row = ch >> 4, c = ch & 15;
            cpa16(sb + row * AT_PITCH + c * 16, ph + row * 256 + c * 16);
        }
        CPA_COMMIT; CPA_WAIT0;
    }
    __syncthreads();

    uint32_t qfh[8][4];
    {
        int arow = w * 16 + (grp & 1) * 8 + r8;
#pragma unroll
        for (int kt = 0; kt < 8; kt++) {
            uint32_t ao = (uint32_t)arow * AT_PITCH + kt * 32 + (grp >> 1) * 16;
            ldsm4(qfh[kt], sb + ao);
        }
    }
    __syncthreads();

    float o[16][4];
#pragma unroll
    for (int dt = 0; dt < 16; dt++)
#pragma unroll
        for (int q = 0; q < 4; q++) o[dt][q] = 0.f;
    float run_l[2] = {0.f, 0.f};

    const char* kh = (const char*)(g_kh + base);
    const char* vh = (const char*)(g_vh + base);

    int mt0 = n0 >> 6;
    auto prefetch = [&](int mt, int st) {
        int m0 = mt * 64;
        uint32_t s0 = sb + st * AT_STAGE;
        for (int ch = tid; ch < 1024; ch += 256) {
            int row = ch >> 4, c = ch & 15;
            uint32_t so = row * AT_PITCH + c * 16;
            size_t go = (size_t)(m0 + row) * 256 + c * 16;
            cpa16(s0 + AT_KH + so, kh + go);
            cpa16(s0 + AT_VH + so, vh + go);
        }
        CPA_COMMIT;
    };
    prefetch(mt0, 0);

    for (int mt = mt0; mt < NN / 64; mt++) {
        int st = (mt - mt0) & 1;
        if (mt + 1 < NN / 64) { prefetch(mt + 1, st ^ 1); CPA_WAIT1; }
        else                  { CPA_WAIT0; }
        __syncthreads();

        uint32_t stb = sb + st * AT_STAGE;
        int m0 = mt * 64;

        // ---- S = Q K^T (hi-only, 64 MMAs) ----
        float s[8][4];
#pragma unroll
        for (int nt = 0; nt < 8; nt++)
#pragma unroll
            for (int q = 0; q < 4; q++) s[nt][q] = 0.f;
#pragma unroll
        for (int kt = 0; kt < 8; kt++) {
            uint32_t bh_[4][4];
#pragma unroll
            for (int ng = 0; ng < 4; ng++) {
                uint32_t ro = (uint32_t)(ng * 16 + (grp >> 1) * 8 + r8) * AT_PITCH
                            + kt * 32 + (grp & 1) * 16;
                ldsm4(bh_[ng], stb + AT_KH + ro);
            }
#pragma unroll
            for (int ng = 0; ng < 4; ng++)
#pragma unroll
                for (int hf = 0; hf < 2; hf++)
                    mma_bf16(s[ng * 2 + hf], qfh[kt], &bh_[ng][hf * 2]);
        }

        // ---- d = l + l^2/2, l = silu(s)/N, causal mask only ----
#pragma unroll
        for (int hf = 0; hf < 2; hf++) {
            int n = n0 + w * 16 + quad + hf * 8;
            float psum = 0.f;
#pragma unroll
            for (int nt = 0; nt < 8; nt++)
#pragma unroll
                for (int c2 = 0; c2 < 2; c2++) {
                    int m = m0 + nt * 8 + tq * 2 + c2;
                    float sc = s[nt][hf * 2 + c2];
                    float l = __fdividef(sc, 1.f + __expf(-sc)) * INV_N;
                    float d = (m > n) ? fmaf(0.5f * l, l, l) : 0.f;
                    s[nt][hf * 2 + c2] = d;
                    psum += d;
                }
            psum += __shfl_xor_sync(0xffffffffu, psum, 1);
            psum += __shfl_xor_sync(0xffffffffu, psum, 2);
            run_l[hf] += psum;
        }

        // ---- O += D V (D bf16 hi-only; V hi via ldmatrix.trans; 64 MMAs) --
#pragma unroll
        for (int kv = 0; kv < 4; kv++) {
            uint32_t dh[4];
#pragma unroll
            for (int half = 0; half < 2; half++) {
                int nt = kv * 2 + half;
                bf16 h0 = __float2bfloat16(s[nt][0]);
                bf16 h1 = __float2bfloat16(s[nt][1]);
                bf16 h2 = __float2bfloat16(s[nt][2]);
                bf16 h3 = __float2bfloat16(s[nt][3]);
                dh[half * 2 + 0] = pkbf(h0, h1);
                dh[half * 2 + 1] = pkbf(h2, h3);
            }
#pragma unroll
            for (int dg = 0; dg < 8; dg++) {
                uint32_t vfh[4];
                uint32_t ro = (uint32_t)(kv * 16 + (grp & 1) * 8 + r8) * AT_PITCH
                            + dg * 32 + (grp >> 1) * 16;
                ldsm4t(vfh, stb + AT_VH + ro);
#pragma unroll
                for (int hf = 0; hf < 2; hf++)
                    mma_bf16(o[dg * 2 + hf], dh, &vfh[hf * 2]);
            }
        }
        __syncthreads();
    }

    // ---- epilogue: O = (SUF + ctp + O_dev)/(CNT + ckp + sum_d) or meanV ----
#pragma unroll
    for (int hf = 0; hf < 2; hf++) {
        int rloc = w * 16 + quad + hf * 8;
        int n = n0 + rloc;
        int validn = (ids[b * NN + n] != 0);
        int ckn = n >> 8;                       // n / CKR
        float cnt = g_cnt[bh * NN + n] + g_ckp[bh * NCK + ckn];
        bool fb = (!validn) || (cnt < 0.5f);
        float inv = fb ? 0.f : 1.f / (cnt + run_l[hf]);
        const float* sufp = g_suf + ((size_t)bh * NN + n) * 128;
        const float* ctpp = g_ctp + (size_t)(bh * NCK + ckn) * 128;
        const float* mvp = g_mv + bh * 128;
        size_t orow = (size_t)(b * NN + n) * DD + h * 128;
#pragma unroll
        for (int dt = 0; dt < 16; dt++) {
            int d = dt * 8 + tq * 2;
            float x0, x1;
            if (fb) { x0 = mvp[d]; x1 = mvp[d + 1]; }
            else {
                float2 sv = *(const float2*)&sufp[d];
                float2 cv = *(const float2*)&ctpp[d];
                x0 = (sv.x + cv.x + o[dt][hf * 2 + 0]) * inv;
                x1 = (sv.y + cv.y + o[dt][hf * 2 + 1]) * inv;
            }
            bf16 h0, l0, h1, l1;
            split2(x0, h0, l0); split2(x1, h1, l1);
            ushort2 hv = {us(h0), us(h1)};
            ushort2 lv = {us(l0), us(l1)};
            *(ushort2*)&g_ath[orow + d] = hv;
            *(ushort2*)&g_atl[orow + d] = lv;
        }
    }
}

// ---------------- launch ----------------
extern "C" void kernel_launch(void* const* d_in, const int* in_sizes, int n_in,
                              void* d_out, int out_size) {
    const int*   ids  = (const int*)d_in[1];     // past_ids (B,N)
    const float* emb  = (const float*)d_in[2];   // past_embeddings (B,N,D)
    const float* qkvw = (const float*)d_in[3];   // (4,1024,4096)
    const float* qkvb = (const float*)d_in[4];   // (4,4096)
    const float* outw = (const float*)d_in[5];   // (4,1024,1024)
    const float* outb = (const float*)d_in[6];   // (4,1024)
    const float* lng  = (const float*)d_in[7];   // (4,1024)
    const float* lnb  = (const float*)d_in[8];   // (4,1024)
    float* X = (float*)d_out;

    cudaFuncSetAttribute(attn_kernel,
                         cudaFuncAttributeMaxDynamicSharedMemorySize, ATTN_SMEM);
    cudaFuncSetAttribute(hmma_gemm<0>,
                         cudaFuncAttributeMaxDynamicSharedMemorySize, HM_SMEM0);
    cudaFuncSetAttribute(hmma_gemm<1>,
                         cudaFuncAttributeMaxDynamicSharedMemorySize, HM_SMEM12);
    cudaFuncSetAttribute(hmma_gemm<2>,
                         cudaFuncAttributeMaxDynamicSharedMemorySize, HM_SMEM12);

    cudaStream_t side;
    cudaStreamCreateWithFlags(&side, cudaStreamNonBlocking);
    cudaEvent_t evF[NBLK], evJ[NBLK];
    for (int l = 0; l < NBLK; l++) {
        cudaEventCreateWithFlags(&evF[l], cudaEventDisableTiming);
        cudaEventCreateWithFlags(&evJ[l], cudaEventDisableTiming);
    }

    cudaMemcpyAsync(X, emb, sizeof(float) * (size_t)MM * DD,
                    cudaMemcpyDeviceToDevice);

    wq_cvt<<<dim3(32, 96, NBLK), dim3(32, 8)>>>(qkvw);
    w2_cvt<<<dim3(32, 32, NBLK), dim3(32, 8)>>>(outw);

    for (int l = 0; l < NBLK; l++) {
        ln_kernel<<<MM, 256>>>(X, lng + l * DD, lnb + l * DD);
        cudaEventRecord(evF[l], 0);
        cudaStreamWaitEvent(side, evF[l], 0);
        // main stream: q/k GEMM (invalid keys zeroed)
        hmma_gemm<0><<<dim3(16, 64), 256, HM_SMEM0>>>(l, qkvb + (size_t)l * QKVW, X, ids);
        // side stream: v GEMM -> suffix sums + prefix tables
        hmma_gemm<1><<<dim3(8, 64), 256, HM_SMEM12, side>>>(l, qkvb + (size_t)l * QKVW, X, ids);
        sufA<<<dim3(NCK, BB * HH), 128, 0, side>>>(ids);
        sufB<<<BB * HH, 128, 0, side>>>();
        cudaEventRecord(evJ[l], side);
        cudaStreamWaitEvent(0, evJ[l], 0);
        attn_kernel<<<dim3(NN / 128, HH, BB), 256, ATTN_SMEM>>>(ids);
        hmma_gemm<2><<<dim3(8, 64), 256, HM_SMEM12>>>(l, outb + (size_t)l * DD, X, ids);
    }
}